// round 10
// baseline (speedup 1.0000x reference)
#include <cuda_runtime.h>
#include <math.h>

// Problem constants
#define BB   16
#define CC   768          // channels == sequence length L
#define LL   768
#define DM   64           // d_model
#define DI   128          // d_inner
#define DS   16           // d_state
#define NROW (BB*CC)      // 12288 rows per image / per branch

#define NCH  6            // scan chunks
#define CHL  128          // chunk length
#define STG  64           // smem staging length (2 subs per chunk)

// ---------------- scratch (device globals; allocation-free rule) ------------
__device__ float  g_xz[2u*NROW*256];     // in_proj outputs, (img, b*L+l, 256)
__device__ float2 g_dtx[3u*NROW*DI];     // (softplus dt, silu(conv x)) per branch, scan order
__device__ float  g_bc[3u*NROW*32];      // B/C permuted: row*32 + q*8 + k:
                                         //   k<4 -> B[q+4k], k>=4 -> C[q+4(k-4)]
__device__ float  g_v[DI];               // out_proj_w^T @ post_w  (collapsed epilogue)
__device__ float  g_part[(size_t)NROW*12]; // per (b,l): 12 partials (3 br x 4 dg)
// chunked-scan intermediates
__device__ float  g_P[48u*5*2048];       // per-chunk state decay products
__device__ float  g_q[48u*5*2048];       // per-chunk local end states
// prepped weights (linear, load-friendly layouts)
__device__ float  g_wxp[3u*4608];        // xproj transposed: [br][k*36+j]
__device__ float  g_wcv[3u*512];         // conv w k-major:   [br][kk*128+d]
__device__ float  g_wdt[3u*512];         // dt w r-major:     [br][r*128+d]
__device__ float  g_A  [3u*2048];        // -exp(A_log):      [br][d*16+s]

struct BP { const float *cw, *cb, *xp, *dtw, *dtb, *Alog, *Dp; };
struct AP { BP br[3]; };

// ============================================================================
// Prep kernels (tiny; also place k_front at ncu's captured 4th launch)
// ============================================================================
__global__ __launch_bounds__(256) void k_prep_w(AP P)
{
    int br = blockIdx.x, t = threadIdx.x;
    const BP Bp = P.br[br];
    float* wxp = g_wxp + br*4608;
    for (int i = t; i < 4608; i += 256) {
        int k = i / 36, j = i - k*36;
        wxp[i] = __ldg(Bp.xp + j*128 + k);         // xproj_w[j][k]
    }
    float* wcv = g_wcv + br*512;
    float* wdt = g_wdt + br*512;
    for (int i = t; i < 512; i += 256) {
        int kk = i >> 7, d = i & 127;
        wcv[i] = __ldg(Bp.cw  + d*4 + kk);
        wdt[i] = __ldg(Bp.dtw + d*4 + kk);
    }
}

__global__ __launch_bounds__(256) void k_prep_A(AP P)
{
    int br = blockIdx.x, t = threadIdx.x;
    const float* al = P.br[br].Alog;
    for (int i = t; i < 2048; i += 256) g_A[br*2048 + i] = -expf(__ldg(al + i));
}

__global__ __launch_bounds__(128) void k_prep_v(
    const float* __restrict__ opw, const float* __restrict__ pw)
{
    int t = threadIdx.x;
    float acc = 0.0f;
    #pragma unroll 8
    for (int m = 0; m < 64; m++) acc = fmaf(__ldg(pw + m), __ldg(opw + m*128 + t), acc);
    g_v[t] = acc;
}

// ============================================================================
// Kernel 1 (fused front): pool 32x32->4x4, pre-proj 16->64, LayerNorm, in_proj
// 64->256. grid (12 c-chunks, 16 b, 2 img), 256 thr; 4 row-tiles per block.
// Weights (w[64] regs, pw_s) loaded ONCE per block and reused across 64 rows:
// kills the 100 MB/launch L2->L1 weight re-load that bound the old version.
// ============================================================================
__global__ __launch_bounds__(256) void k_front(
    const float* __restrict__ img1, const float* __restrict__ img2,
    const float* __restrict__ pre_w, const float* __restrict__ pre_b,
    const float* __restrict__ ln_g,  const float* __restrict__ ln_b,
    const float* __restrict__ w0,    const float* __restrict__ w1)
{
    int img = blockIdx.z, b = blockIdx.y;
    const float* imbase = (img ? img2 : img1) + (size_t)b*CC*1024;

    // part_s padded layout: addr(c, t) = c*296 + (t>>6)*72 + (t&63)
    __shared__ float part_s[16*296];
    __shared__ float pw_s[16*64];        // transposed: pw_s[q*64+m]
    __shared__ float pb_s[64], lg_s[64], lb_s[64];
    __shared__ float pool_s[16*16];
    __shared__ __align__(16) float xrow[16*64];

    int t = threadIdx.x;
    // stage pre weights + in_proj W row t (once per block)
    for (int i = t; i < 1024; i += 256) {
        int q = i >> 6, m = i & 63;
        pw_s[i] = __ldg(pre_w + m*16 + q);
    }
    if (t < 64) { pb_s[t] = __ldg(pre_b+t); lg_s[t] = __ldg(ln_g+t); lb_s[t] = __ldg(ln_b+t); }

    float w[64];
    {
        const float4* W4 = (const float4*)((img ? w1 : w0) + t*64);
        #pragma unroll
        for (int q = 0; q < 16; q++) {
            float4 v = __ldg(W4 + q);
            w[4*q]=v.x; w[4*q+1]=v.y; w[4*q+2]=v.z; w[4*q+3]=v.w;
        }
    }

    for (int tile = 0; tile < 4; tile++) {
        int c0 = (blockIdx.x*4 + tile) * 16;
        const float* src = imbase + (size_t)c0 * 1024;
        __syncthreads();                     // prev tile's phase-3 readers done

        // phase 1a: coalesced float4 loads; one partial per load
        {
            const float4* s4 = (const float4*)src;
            int toff = (t >> 6)*72 + (t & 63);
            #pragma unroll
            for (int i = 0; i < 16; i++) {
                float4 a = __ldg(s4 + i*256 + t);
                part_s[i*296 + toff] = (a.x + a.y) + (a.z + a.w);
            }
        }
        __syncthreads();

        // phase 1b: reduce 16 contributors per (channel, cell)
        {
            int c = t >> 4, cell = t & 15;
            int pi = cell >> 2, pj = cell & 3;
            const float* base = part_s + c*296 + pi*72 + 2*pj;
            float s = 0.0f;
            #pragma unroll
            for (int k = 0; k < 8; k++) s += base[8*k] + base[8*k + 1];
            pool_s[c*16 + cell] = s * (1.0f/64.0f);
        }
        __syncthreads();

        // phase 2: pre-proj + LN. 16 threads/row, thread g owns m = g+16k
        {
            int r = t >> 4, g = t & 15;
            float y[4], sum = 0.0f, sq = 0.0f;
            #pragma unroll
            for (int k = 0; k < 4; k++) {
                int m = g + 16*k;
                float acc = pb_s[m];
                #pragma unroll
                for (int q = 0; q < 16; q++)
                    acc = fmaf(pw_s[q*64 + m], pool_s[r*16 + q], acc);
                y[k] = acc; sum += acc; sq = fmaf(acc, acc, sq);
            }
            #pragma unroll
            for (int m = 8; m >= 1; m >>= 1) {
                sum += __shfl_xor_sync(0xffffffffu, sum, m);
                sq  += __shfl_xor_sync(0xffffffffu, sq,  m);
            }
            float mu  = sum * (1.0f/64.0f);
            float var = sq  * (1.0f/64.0f) - mu*mu;
            float rs  = rsqrtf(var + 1e-5f);
            #pragma unroll
            for (int k = 0; k < 4; k++) {
                int m = g + 16*k;
                xrow[r*64 + m] = (y[k] - mu)*rs*lg_s[m] + lb_s[m];
            }
        }
        __syncthreads();

        // phase 3: xz GEMM. thread owns output column t; W in registers.
        {
            float* xzout = g_xz + (size_t)img*NROW*256 + ((size_t)(b*CC + c0))*256;
            for (int r4 = 0; r4 < 16; r4 += 4) {
                float a0=0.f, a1=0.f, a2=0.f, a3=0.f;
                #pragma unroll
                for (int q = 0; q < 16; q++) {
                    float4 x0 = *(const float4*)&xrow[(r4+0)*64 + q*4];
                    float4 x1 = *(const float4*)&xrow[(r4+1)*64 + q*4];
                    float4 x2 = *(const float4*)&xrow[(r4+2)*64 + q*4];
                    float4 x3 = *(const float4*)&xrow[(r4+3)*64 + q*4];
                    a0 = fmaf(x0.x,w[4*q],a0); a0 = fmaf(x0.y,w[4*q+1],a0);
                    a0 = fmaf(x0.z,w[4*q+2],a0); a0 = fmaf(x0.w,w[4*q+3],a0);
                    a1 = fmaf(x1.x,w[4*q],a1); a1 = fmaf(x1.y,w[4*q+1],a1);
                    a1 = fmaf(x1.z,w[4*q+2],a1); a1 = fmaf(x1.w,w[4*q+3],a1);
                    a2 = fmaf(x2.x,w[4*q],a2); a2 = fmaf(x2.y,w[4*q+1],a2);
                    a2 = fmaf(x2.z,w[4*q+2],a2); a2 = fmaf(x2.w,w[4*q+3],a2);
                    a3 = fmaf(x3.x,w[4*q],a3); a3 = fmaf(x3.y,w[4*q+1],a3);
                    a3 = fmaf(x3.z,w[4*q+2],a3); a3 = fmaf(x3.w,w[4*q+3],a3);
                }
                xzout[(size_t)(r4+0)*256 + t] = a0;
                xzout[(size_t)(r4+1)*256 + t] = a1;
                xzout[(size_t)(r4+2)*256 + t] = a2;
                xzout[(size_t)(r4+3)*256 + t] = a3;
            }
        }
    }
}

// ============================================================================
// Kernel 3: causal depthwise conv(K=4)+silu, x-proj (128->36), dt-proj+softplus.
// ============================================================================
__global__ __launch_bounds__(256) void k_conv_proj(AP P)
{
    int br = blockIdx.z, b = blockIdx.y;
    int p0 = blockIdx.x * 32;
    const BP Bp = P.br[br];

    __shared__ __align__(16) float xs[35*128];
    __shared__ __align__(16) float xp_s[128*36];
    __shared__ float dbc_s[32*36];
    __shared__ __align__(16) float cw_s[512];
    __shared__ __align__(16) float dtw_s[512];
    __shared__ __align__(16) float cb_s[128], dtb_s[128];

    int t = threadIdx.x;
    {   // vectorized weight staging from prepped linear arrays (L2-hot)
        const float4* wsrc = (const float4*)(g_wxp + br*4608);
        #pragma unroll
        for (int i0 = 0; i0 < 1152; i0 += 256) ((float4*)xp_s)[i0 + t] = wsrc[i0 + t];
        if (t < 128)       ((float4*)cw_s )[t]     = ((const float4*)(g_wcv + br*512))[t];
        else               ((float4*)dtw_s)[t-128] = ((const float4*)(g_wdt + br*512))[t-128];
        if (t < 32)        ((float4*)cb_s )[t]     = __ldg((const float4*)Bp.cb  + t);
        else if (t < 64)   ((float4*)dtb_s)[t-32]  = __ldg((const float4*)Bp.dtb + (t-32));
    }

    const float* xzsrc = g_xz + ((br == 2) ? (size_t)NROW*256 : 0);
    for (int i = t; i < 35*128; i += 256) {
        int r = i >> 7, d = i & 127;
        int p = p0 - 3 + r;
        float v = 0.0f;
        if (p >= 0) {
            int l = (br == 1) ? (767 - p) : p;
            v = xzsrc[(size_t)(b*LL + l)*256 + d];
        }
        xs[i] = v;
    }
    __syncthreads();

    // causal depthwise conv + silu
    float xc[16];
    #pragma unroll
    for (int it = 0; it < 16; it++) {
        int i = t + it*256;
        int p = i >> 7, d = i & 127;
        float acc = cb_s[d];
        #pragma unroll
        for (int kk = 0; kk < 4; kk++)
            acc = fmaf(cw_s[kk*128 + d], xs[(p+kk)*128 + d], acc);
        float sg = 1.0f / (1.0f + __expf(-acc));
        xc[it] = acc * sg;
    }
    __syncthreads();
    #pragma unroll
    for (int it = 0; it < 16; it++) {
        int i = t + it*256;
        int p = i >> 7, d = i & 127;
        xs[(p+3)*128 + d] = xc[it];
    }
    __syncthreads();

    // B/C GEMM: 32 rows x 32 cols (j=4..35), 2x2 tiles, all 256 threads
    {
        int pg = t >> 4, jg = t & 15;
        int p = 2*pg, j = 4 + 2*jg;
        float a00=0.f, a01=0.f, a10=0.f, a11=0.f;
        const float* xr0 = xs + (p+3)*128;
        const float* xr1 = xs + (p+4)*128;
        const float* wc  = xp_s + j;
        #pragma unroll 4
        for (int k = 0; k < 128; k += 2) {
            float2 x0 = *(const float2*)&xr0[k];
            float2 x1 = *(const float2*)&xr1[k];
            float2 u0 = *(const float2*)&wc[k*36];
            float2 u1 = *(const float2*)&wc[(k+1)*36];
            a00 = fmaf(x0.x, u0.x, a00); a01 = fmaf(x0.x, u0.y, a01);
            a10 = fmaf(x1.x, u0.x, a10); a11 = fmaf(x1.x, u0.y, a11);
            a00 = fmaf(x0.y, u1.x, a00); a01 = fmaf(x0.y, u1.y, a01);
            a10 = fmaf(x1.y, u1.x, a10); a11 = fmaf(x1.y, u1.y, a11);
        }
        dbc_s[p*36 + j]       = a00;
        dbc_s[p*36 + j + 1]   = a01;
        dbc_s[(p+1)*36 + j]   = a10;
        dbc_s[(p+1)*36 + j+1] = a11;
    }
    // dt columns (j=0..3): 128 outputs, split-k (2 threads each)
    {
        int oi = t >> 1, half = t & 1;
        int p = oi >> 2, j = oi & 3;
        const float* xr = xs + (p+3)*128 + half*64;
        const float* wc = xp_s + (half*64)*36 + j;
        float acc = 0.0f;
        #pragma unroll 8
        for (int k = 0; k < 64; k += 2) {
            float2 x = *(const float2*)&xr[k];
            acc = fmaf(x.x, wc[k*36],     acc);
            acc = fmaf(x.y, wc[(k+1)*36], acc);
        }
        acc += __shfl_xor_sync(0xffffffffu, acc, 1);
        if (half == 0) dbc_s[p*36 + j] = acc;
    }
    __syncthreads();

    // dt = softplus(dbc[:4] @ dtw^T + dtb); write fused (dt, xconv) float2
    size_t obase = (size_t)((br*BB + b)*LL + p0) * DI;
    #pragma unroll
    for (int it = 0; it < 16; it++) {
        int i = t + it*256;
        int p = i >> 7, d = i & 127;
        float acc = dtb_s[d];
        #pragma unroll
        for (int r = 0; r < 4; r++)
            acc = fmaf(dtw_s[r*128 + d], dbc_s[p*36 + r], acc);
        float sp = (acc > 20.0f) ? acc : log1pf(__expf(acc));
        g_dtx[obase + i] = make_float2(sp, xs[(p+3)*128 + d]);
    }
    // B/C permuted: row*32 + q*8 + k
    size_t sbase = (size_t)((br*BB + b)*LL + p0) * 32;
    for (int i = t; i < 1024; i += 256) {
        int p = i >> 5, c = i & 31;
        int q = c >> 3, k = c & 7;
        float v = (k < 4) ? dbc_s[p*36 + 4  + q + 4*k]
                          : dbc_s[p*36 + 20 + q + 4*(k-4)];
        g_bc[sbase + i] = v;
    }
}

// ============================================================================
// Kernel 4a: scan pass 1 — per-chunk (P, q), chunks 0..4.
// grid (4 dg * 5 ch, 16, 3) = 960 blocks, 128 thr = 32 d x 4 q.
// ============================================================================
__global__ __launch_bounds__(128) void k_scan1(AP P)
{
    int bx = blockIdx.x;
    int dg = bx / 5, ch = bx - dg*5;
    int b = blockIdx.y, br = blockIdx.z;
    int d0 = dg * 32;
    int t  = threadIdx.x;
    int dl = t >> 2, q = t & 3;
    int d  = d0 + dl;

    float A[4], h[4] = {0,0,0,0}, Pp[4] = {1,1,1,1};
    #pragma unroll
    for (int k = 0; k < 4; k++) A[k] = __ldg(g_A + br*2048 + d*DS + q + 4*k);

    __shared__ __align__(16) float2 sdtx[STG*32];
    __shared__ __align__(16) float  sb[STG*16];

    int bb = br*BB + b;
    size_t rbase = (size_t)bb * LL;

    for (int sub = 0; sub < 2; sub++) {
        int q0 = ch*CHL + sub*STG;
        __syncthreads();
        for (int i = t; i < STG*32; i += 128) {
            int tt = i >> 5, dd = i & 31;
            sdtx[i] = g_dtx[(rbase + q0 + tt)*DI + d0 + dd];
        }
        for (int i = t; i < STG*16; i += 128) {
            int tt = i >> 4, c = i & 15;
            sb[i] = g_bc[(rbase + q0 + tt)*32 + (c>>2)*8 + (c&3)];
        }
        __syncthreads();

        for (int tb = 0; tb < STG; tb += 4) {
            float2 dx[4]; float4 bq[4];
            #pragma unroll
            for (int j = 0; j < 4; j++) {
                dx[j] = sdtx[(tb+j)*32 + dl];
                bq[j] = *(const float4*)&sb[((tb+j)*4 + q)*4];
            }
            float e[4][4];
            #pragma unroll
            for (int j = 0; j < 4; j++) {
                e[j][0] = __expf(dx[j].x*A[0]);
                e[j][1] = __expf(dx[j].x*A[1]);
                e[j][2] = __expf(dx[j].x*A[2]);
                e[j][3] = __expf(dx[j].x*A[3]);
            }
            #pragma unroll
            for (int j = 0; j < 4; j++) {
                float u = dx[j].x * dx[j].y;
                h[0] = fmaf(e[j][0], h[0], bq[j].x * u);
                h[1] = fmaf(e[j][1], h[1], bq[j].y * u);
                h[2] = fmaf(e[j][2], h[2], bq[j].z * u);
                h[3] = fmaf(e[j][3], h[3], bq[j].w * u);
            }
            #pragma unroll
            for (int k = 0; k < 4; k++)
                Pp[k] *= (e[0][k]*e[1][k])*(e[2][k]*e[3][k]);
        }
    }
    size_t pidx = ((size_t)(bb*5 + ch))*2048 + (size_t)d*16 + q;
    #pragma unroll
    for (int k = 0; k < 4; k++) {
        g_P[pidx + 4*k] = Pp[k];
        g_q[pidx + 4*k] = h[k];
    }
}

// ============================================================================
// Kernel 4b: scan pass 2 — inline boundary combine; per-(row,dg) partial dots
// against v. grid (4 dg * 6 ch, 16, 3) = 1152 blocks, 128 thr.
// ============================================================================
__global__ __launch_bounds__(128) void k_scan2(AP P)
{
    int bx = blockIdx.x;
    int dg = bx / 6, ch = bx - dg*6;
    int b = blockIdx.y, br = blockIdx.z;
    int d0 = dg * 32;
    int t  = threadIdx.x;
    int dl = t >> 2, q = t & 3;
    int d  = d0 + dl;
    const BP Bp = P.br[br];

    float A[4];
    #pragma unroll
    for (int k = 0; k < 4; k++) A[k] = __ldg(g_A + br*2048 + d*DS + q + 4*k);
    float Dp = __ldg(Bp.Dp + d);

    int bb = br*BB + b;
    float h[4] = {0,0,0,0};
    for (int c = 0; c < ch; c++) {
        size_t s = ((size_t)(bb*5 + c))*2048 + (size_t)d*16 + q;
        #pragma unroll
        for (int k = 0; k < 4; k++)
            h[k] = fmaf(g_P[s + 4*k], h[k], g_q[s + 4*k]);
    }

    __shared__ __align__(16) float2 sdtx[STG*32];
    __shared__ __align__(16) float  sbc[STG*32];
    __shared__ float sy[STG*32];
    __shared__ float v_s[32];

    if (t < 32) v_s[t] = g_v[d0 + t];

    size_t rbase = (size_t)bb * LL;
    const float* zsrc = g_xz + ((br == 2) ? (size_t)NROW*256 : 0)
                             + (size_t)b*LL*256 + 128 + d0;
    const int rev  = (br == 1);
    const int lb   = rev ? 767 : 0;
    const int lsgn = rev ? -1 : 1;

    for (int sub = 0; sub < 2; sub++) {
        int q0 = ch*CHL + sub*STG;
        __syncthreads();
        for (int i = t; i < STG*32; i += 128) {
            int tt = i >> 5, dd = i & 31;
            sdtx[i] = g_dtx[(rbase + q0 + tt)*DI + d0 + dd];
            sbc[i]  = g_bc [(rbase + q0 + tt)*32 + dd];
        }
        __syncthreads();

        for (int tb = 0; tb < STG; tb += 4) {
            float2 dx[4]; float4 bq[4], cq[4]; float py[4];
            #pragma unroll
            for (int j = 0; j < 4; j++) {
                dx[j] = sdtx[(tb+j)*32 + dl];
                bq[j] = *(const float4*)&sbc[(tb+j)*32 + q*8];
                cq[j] = *(const float4*)&sbc[(tb+j)*32 + q*8 + 4];
            }
            float e[4][4];
            #pragma unroll
            for (int j = 0; j < 4; j++) {
                e[j][0] = __expf(dx[j].x*A[0]);
                e[j][1] = __expf(dx[j].x*A[1]);
                e[j][2] = __expf(dx[j].x*A[2]);
                e[j][3] = __expf(dx[j].x*A[3]);
            }
            #pragma unroll
            for (int j = 0; j < 4; j++) {
                float u = dx[j].x * dx[j].y;
                h[0] = fmaf(e[j][0], h[0], bq[j].x * u);
                h[1] = fmaf(e[j][1], h[1], bq[j].y * u);
                h[2] = fmaf(e[j][2], h[2], bq[j].z * u);
                h[3] = fmaf(e[j][3], h[3], bq[j].w * u);
                float p = h[0]*cq[j].x;
                p = fmaf(h[1], cq[j].y, p);
                p = fmaf(h[2], cq[j].z, p);
                py[j] = fmaf(h[3], cq[j].w, p);
            }
            #pragma unroll
            for (int j = 0; j < 4; j++) {
                py[j] += __shfl_xor_sync(0xffffffffu, py[j], 2);
                py[j] += __shfl_xor_sync(0xffffffffu, py[j], 1);
            }
            if (q == 0) {
                #pragma unroll
                for (int j = 0; j < 4; j++)
                    sy[(tb+j)*32 + dl] = fmaf(dx[j].y, Dp, py[j]);
            }
        }
        __syncthreads();

        // gated partial dot with v: 2 threads per row, 16 d's each
        {
            int row  = t >> 1, half = t & 1;
            int qq   = q0 + row;
            int l    = lb + lsgn*qq;
            const float* zr = zsrc + (size_t)l*256 + half*16;
            const float* yr = sy + row*32 + half*16;
            const float* vr = v_s + half*16;
            float acc = 0.0f;
            #pragma unroll
            for (int dd = 0; dd < 16; dd++) {
                float zv = zr[dd];
                float sg = zv / (1.0f + __expf(-zv));
                acc = fmaf(yr[dd]*sg, vr[dd], acc);
            }
            acc += __shfl_xor_sync(0xffffffffu, acc, 1);
            if (half == 0)
                g_part[((size_t)(b*LL + l))*12 + br*4 + dg] = acc;
        }
    }
}

// ============================================================================
// Kernel 5: att = sigmoid((sum of 12 partials + post_b)/2) + 1e-6
// ============================================================================
__global__ __launch_bounds__(256) void k_final(
    const float* __restrict__ pb, float* __restrict__ out)
{
    int row = blockIdx.x*256 + threadIdx.x;
    const float4* p = (const float4*)(g_part + (size_t)row*12);
    float4 a = p[0], b4 = p[1], c = p[2];
    float s = (a.x+a.y)+(a.z+a.w) + (b4.x+b4.y)+(b4.z+b4.w) + (c.x+c.y)+(c.z+c.w);
    float o = (s + __ldg(pb)) * 0.5f;
    out[row] = 1.0f / (1.0f + __expf(-o)) + 1e-6f;
}

// ============================================================================
extern "C" void kernel_launch(void* const* d_in, const int* in_sizes, int n_in,
                              void* d_out, int out_size)
{
    const float* img1 = (const float*)d_in[0];
    const float* img2 = (const float*)d_in[1];
    const float* pre_w = (const float*)d_in[2];
    const float* pre_b = (const float*)d_in[3];
    const float* ln_g  = (const float*)d_in[4];
    const float* ln_b  = (const float*)d_in[5];
    const float* in_proj_w   = (const float*)d_in[6];
    const float* in_proj_s_w = (const float*)d_in[7];
    const float* out_proj_w  = (const float*)d_in[8];
    const float* post_w = (const float*)d_in[9];
    const float* post_b = (const float*)d_in[10];

    AP P;
    for (int t = 0; t < 3; t++) {
        int o = 11 + 7*t;              // f, b, s
        P.br[t].cw   = (const float*)d_in[o+0];
        P.br[t].cb   = (const float*)d_in[o+1];
        P.br[t].xp   = (const float*)d_in[o+2];
        P.br[t].dtw  = (const float*)d_in[o+3];
        P.br[t].dtb  = (const float*)d_in[o+4];
        P.br[t].Alog = (const float*)d_in[o+5];
        P.br[t].Dp   = (const float*)d_in[o+6];
    }

    k_prep_w<<<3, 256>>>(P);
    k_prep_A<<<3, 256>>>(P);
    k_prep_v<<<1, 128>>>(out_proj_w, post_w);
    k_front<<<dim3(12, 16, 2), 256>>>(img1, img2, pre_w, pre_b, ln_g, ln_b,
                                      in_proj_w, in_proj_s_w);
    k_conv_proj<<<dim3(24, 16, 3), 256>>>(P);
    k_scan1<<<dim3(20, 16, 3), 128>>>(P);
    k_scan2<<<dim3(24, 16, 3), 128>>>(P);
    k_final<<<48, 256>>>(post_b, (float*)d_out);
    (void)in_sizes; (void)n_in; (void)out_size;
}

// round 12
// speedup vs baseline: 1.1829x; 1.1829x over previous
#include <cuda_runtime.h>
#include <math.h>

// Problem constants
#define BB   16
#define CC   768          // channels == sequence length L
#define LL   768
#define DM   64           // d_model
#define DI   128          // d_inner
#define DS   16           // d_state
#define NROW (BB*CC)      // 12288 rows per image / per branch

#define NCH  6            // scan chunks
#define CHL  128          // chunk length
#define STG  64           // smem staging length (2 subs per chunk)

// ---------------- scratch (device globals; allocation-free rule) ------------
__device__ float  g_xz[2u*NROW*256];     // in_proj outputs, (img, b*L+l, 256)
__device__ float2 g_dtx[3u*NROW*DI];     // (softplus dt, silu(conv x)) per branch, scan order
__device__ float  g_bc[3u*NROW*32];      // B/C permuted: row*32 + q*8 + k
__device__ float  g_v[DI];               // out_proj_w^T @ post_w  (collapsed epilogue)
__device__ float  g_part[(size_t)NROW*12]; // per (b,l): 12 partials (3 br x 4 dg)
// chunked-scan intermediates
__device__ float  g_P[48u*5*2048];       // per-chunk state decay products
__device__ float  g_q[48u*5*2048];       // per-chunk local end states
// prepped weights (linear / transposed, load-friendly layouts)
__device__ float  g_wxp[3u*4608];        // xproj transposed: [br][k*36+j]
__device__ float  g_wcv[3u*512];         // conv w k-major:   [br][kk*128+d]
__device__ float  g_wdt[3u*512];         // dt w r-major:     [br][r*128+d]
__device__ float  g_A  [3u*2048];        // -exp(A_log):      [br][d*16+s]
__device__ float  g_wi [2u*16384];       // in_proj transposed for coalesced
                                         // per-thread loads: f4[img][q*256+t] = W[t][4q..4q+3]
__device__ float  g_pwt[1024];           // pre_w transposed: [q*64+m]

struct BP { const float *cw, *cb, *xp, *dtw, *dtb, *Alog, *Dp; };
struct AP { BP br[3]; };

// ============================================================================
// Prep kernels (tiny, one-time; keep k_front as ncu's captured 4th launch)
// ============================================================================
__global__ __launch_bounds__(256) void k_prep_w(AP P)
{
    int br = blockIdx.x, t = threadIdx.x;
    const BP Bp = P.br[br];
    float* wxp = g_wxp + br*4608;
    for (int i = t; i < 4608; i += 256) {
        int k = i / 36, j = i - k*36;
        wxp[i] = __ldg(Bp.xp + j*128 + k);         // xproj_w[j][k]
    }
    float* wcv = g_wcv + br*512;
    float* wdt = g_wdt + br*512;
    for (int i = t; i < 512; i += 256) {
        int kk = i >> 7, d = i & 127;
        wcv[i] = __ldg(Bp.cw  + d*4 + kk);
        wdt[i] = __ldg(Bp.dtw + d*4 + kk);
    }
}

// blocks 0-2: -exp(A_log) per branch; blocks 3-4: in_proj/pre_w transposes
__global__ __launch_bounds__(256) void k_prep_A(AP P,
    const float* __restrict__ w0, const float* __restrict__ w1,
    const float* __restrict__ pre_w)
{
    int bx = blockIdx.x, t = threadIdx.x;
    if (bx < 3) {
        const float* al = P.br[bx].Alog;
        for (int i = t; i < 2048; i += 256) g_A[bx*2048 + i] = -expf(__ldg(al + i));
    } else {
        int img = bx - 3;
        const float4* W4 = (const float4*)(img ? w1 : w0);
        float4* dst = (float4*)(g_wi + (size_t)img*16384);
        #pragma unroll
        for (int q = 0; q < 16; q++)
            dst[q*256 + t] = __ldg(W4 + t*16 + q);   // [q][t] = W[t][4q..]
        if (img == 0) {
            for (int i = t; i < 1024; i += 256) {
                int q = i >> 6, m = i & 63;
                g_pwt[i] = __ldg(pre_w + m*16 + q);
            }
        }
    }
}

__global__ __launch_bounds__(128) void k_prep_v(
    const float* __restrict__ opw, const float* __restrict__ pw)
{
    int t = threadIdx.x;
    float acc = 0.0f;
    #pragma unroll 8
    for (int m = 0; m < 64; m++) acc = fmaf(__ldg(pw + m), __ldg(opw + m*128 + t), acc);
    g_v[t] = acc;
}

// ============================================================================
// Kernel 1 (fused front): pool 32x32->4x4, pre-proj 16->64, LayerNorm, in_proj
// 64->256. grid (48 c-chunks, 16 b, 2 img), 256 threads (R9 structure).
// Weight loads COALESCED via the transposed g_wi/g_pwt layouts:
// one wavefront per load instruction instead of 32.
// ============================================================================
__global__ __launch_bounds__(256) void k_front(
    const float* __restrict__ img1, const float* __restrict__ img2,
    const float* __restrict__ pre_b,
    const float* __restrict__ ln_g,  const float* __restrict__ ln_b)
{
    int img = blockIdx.z, b = blockIdx.y, c0 = blockIdx.x * 16;
    const float* src = (img ? img2 : img1) + ((size_t)(b*CC + c0)) * 1024;

    // part_s padded layout: addr(c, t) = c*296 + (t>>6)*72 + (t&63)
    __shared__ float part_s[16*296];
    __shared__ float pw_s[16*64];        // transposed: pw_s[q*64+m]
    __shared__ float pb_s[64], lg_s[64], lb_s[64];
    __shared__ float pool_s[16*16];
    __shared__ __align__(16) float xrow[16*64];

    int t = threadIdx.x;
    // stage pre weights (linear, coalesced from prepped transpose)
    for (int i = t; i < 1024; i += 256) pw_s[i] = g_pwt[i];
    if (t < 64) { pb_s[t] = __ldg(pre_b+t); lg_s[t] = __ldg(ln_g+t); lb_s[t] = __ldg(ln_b+t); }

    // in_proj W row t, loaded coalesced from transposed layout
    float w[64];
    {
        const float4* W4 = (const float4*)(g_wi + (size_t)img*16384);
        #pragma unroll
        for (int q = 0; q < 16; q++) {
            float4 v = W4[q*256 + t];
            w[4*q]=v.x; w[4*q+1]=v.y; w[4*q+2]=v.z; w[4*q+3]=v.w;
        }
    }

    // phase 1a: coalesced float4 loads; one partial per load
    {
        const float4* s4 = (const float4*)src;
        int toff = (t >> 6)*72 + (t & 63);
        #pragma unroll
        for (int i = 0; i < 16; i++) {
            float4 a = __ldg(s4 + i*256 + t);
            part_s[i*296 + toff] = (a.x + a.y) + (a.z + a.w);
        }
    }
    __syncthreads();

    // phase 1b: reduce 16 contributors per (channel, cell)
    {
        int c = t >> 4, cell = t & 15;
        int pi = cell >> 2, pj = cell & 3;
        const float* base = part_s + c*296 + pi*72 + 2*pj;
        float s = 0.0f;
        #pragma unroll
        for (int k = 0; k < 8; k++) s += base[8*k] + base[8*k + 1];
        pool_s[c*16 + cell] = s * (1.0f/64.0f);
    }
    __syncthreads();

    // phase 2: pre-proj + LN. 16 threads/row, thread g owns m = g+16k
    {
        int r = t >> 4, g = t & 15;
        float y[4], sum = 0.0f, sq = 0.0f;
        #pragma unroll
        for (int k = 0; k < 4; k++) {
            int m = g + 16*k;
            float acc = pb_s[m];
            #pragma unroll
            for (int q = 0; q < 16; q++)
                acc = fmaf(pw_s[q*64 + m], pool_s[r*16 + q], acc);
            y[k] = acc; sum += acc; sq = fmaf(acc, acc, sq);
        }
        #pragma unroll
        for (int m = 8; m >= 1; m >>= 1) {
            sum += __shfl_xor_sync(0xffffffffu, sum, m);
            sq  += __shfl_xor_sync(0xffffffffu, sq,  m);
        }
        float mu  = sum * (1.0f/64.0f);
        float var = sq  * (1.0f/64.0f) - mu*mu;
        float rs  = rsqrtf(var + 1e-5f);
        #pragma unroll
        for (int k = 0; k < 4; k++) {
            int m = g + 16*k;
            xrow[r*64 + m] = (y[k] - mu)*rs*lg_s[m] + lb_s[m];
        }
    }
    __syncthreads();

    // phase 3: xz GEMM. thread owns output column t; W in registers.
    {
        float* xzout = g_xz + (size_t)img*NROW*256 + ((size_t)(b*CC + c0))*256;
        for (int r4 = 0; r4 < 16; r4 += 4) {
            float a0=0.f, a1=0.f, a2=0.f, a3=0.f;
            #pragma unroll
            for (int q = 0; q < 16; q++) {
                float4 x0 = *(const float4*)&xrow[(r4+0)*64 + q*4];
                float4 x1 = *(const float4*)&xrow[(r4+1)*64 + q*4];
                float4 x2 = *(const float4*)&xrow[(r4+2)*64 + q*4];
                float4 x3 = *(const float4*)&xrow[(r4+3)*64 + q*4];
                a0 = fmaf(x0.x,w[4*q],a0); a0 = fmaf(x0.y,w[4*q+1],a0);
                a0 = fmaf(x0.z,w[4*q+2],a0); a0 = fmaf(x0.w,w[4*q+3],a0);
                a1 = fmaf(x1.x,w[4*q],a1); a1 = fmaf(x1.y,w[4*q+1],a1);
                a1 = fmaf(x1.z,w[4*q+2],a1); a1 = fmaf(x1.w,w[4*q+3],a1);
                a2 = fmaf(x2.x,w[4*q],a2); a2 = fmaf(x2.y,w[4*q+1],a2);
                a2 = fmaf(x2.z,w[4*q+2],a2); a2 = fmaf(x2.w,w[4*q+3],a2);
                a3 = fmaf(x3.x,w[4*q],a3); a3 = fmaf(x3.y,w[4*q+1],a3);
                a3 = fmaf(x3.z,w[4*q+2],a3); a3 = fmaf(x3.w,w[4*q+3],a3);
            }
            xzout[(size_t)(r4+0)*256 + t] = a0;
            xzout[(size_t)(r4+1)*256 + t] = a1;
            xzout[(size_t)(r4+2)*256 + t] = a2;
            xzout[(size_t)(r4+3)*256 + t] = a3;
        }
    }
}

// ============================================================================
// Kernel 3: causal depthwise conv(K=4)+silu, x-proj (128->36), dt-proj+softplus.
// ============================================================================
__global__ __launch_bounds__(256) void k_conv_proj(AP P)
{
    int br = blockIdx.z, b = blockIdx.y;
    int p0 = blockIdx.x * 32;
    const BP Bp = P.br[br];

    __shared__ __align__(16) float xs[35*128];
    __shared__ __align__(16) float xp_s[128*36];
    __shared__ float dbc_s[32*36];
    __shared__ __align__(16) float cw_s[512];
    __shared__ __align__(16) float dtw_s[512];
    __shared__ __align__(16) float cb_s[128], dtb_s[128];

    int t = threadIdx.x;
    {   // vectorized weight staging from prepped linear arrays (L2-hot)
        const float4* wsrc = (const float4*)(g_wxp + br*4608);
        #pragma unroll
        for (int i0 = 0; i0 < 1152; i0 += 256) ((float4*)xp_s)[i0 + t] = wsrc[i0 + t];
        if (t < 128)       ((float4*)cw_s )[t]     = ((const float4*)(g_wcv + br*512))[t];
        else               ((float4*)dtw_s)[t-128] = ((const float4*)(g_wdt + br*512))[t-128];
        if (t < 32)        ((float4*)cb_s )[t]     = __ldg((const float4*)Bp.cb  + t);
        else if (t < 64)   ((float4*)dtb_s)[t-32]  = __ldg((const float4*)Bp.dtb + (t-32));
    }

    const float* xzsrc = g_xz + ((br == 2) ? (size_t)NROW*256 : 0);
    for (int i = t; i < 35*128; i += 256) {
        int r = i >> 7, d = i & 127;
        int p = p0 - 3 + r;
        float v = 0.0f;
        if (p >= 0) {
            int l = (br == 1) ? (767 - p) : p;
            v = xzsrc[(size_t)(b*LL + l)*256 + d];
        }
        xs[i] = v;
    }
    __syncthreads();

    // causal depthwise conv + silu
    float xc[16];
    #pragma unroll
    for (int it = 0; it < 16; it++) {
        int i = t + it*256;
        int p = i >> 7, d = i & 127;
        float acc = cb_s[d];
        #pragma unroll
        for (int kk = 0; kk < 4; kk++)
            acc = fmaf(cw_s[kk*128 + d], xs[(p+kk)*128 + d], acc);
        float sg = 1.0f / (1.0f + __expf(-acc));
        xc[it] = acc * sg;
    }
    __syncthreads();
    #pragma unroll
    for (int it = 0; it < 16; it++) {
        int i = t + it*256;
        int p = i >> 7, d = i & 127;
        xs[(p+3)*128 + d] = xc[it];
    }
    __syncthreads();

    // B/C GEMM: 32 rows x 32 cols (j=4..35), 2x2 tiles, all 256 threads
    {
        int pg = t >> 4, jg = t & 15;
        int p = 2*pg, j = 4 + 2*jg;
        float a00=0.f, a01=0.f, a10=0.f, a11=0.f;
        const float* xr0 = xs + (p+3)*128;
        const float* xr1 = xs + (p+4)*128;
        const float* wc  = xp_s + j;
        #pragma unroll 4
        for (int k = 0; k < 128; k += 2) {
            float2 x0 = *(const float2*)&xr0[k];
            float2 x1 = *(const float2*)&xr1[k];
            float2 u0 = *(const float2*)&wc[k*36];
            float2 u1 = *(const float2*)&wc[(k+1)*36];
            a00 = fmaf(x0.x, u0.x, a00); a01 = fmaf(x0.x, u0.y, a01);
            a10 = fmaf(x1.x, u0.x, a10); a11 = fmaf(x1.x, u0.y, a11);
            a00 = fmaf(x0.y, u1.x, a00); a01 = fmaf(x0.y, u1.y, a01);
            a10 = fmaf(x1.y, u1.x, a10); a11 = fmaf(x1.y, u1.y, a11);
        }
        dbc_s[p*36 + j]       = a00;
        dbc_s[p*36 + j + 1]   = a01;
        dbc_s[(p+1)*36 + j]   = a10;
        dbc_s[(p+1)*36 + j+1] = a11;
    }
    // dt columns (j=0..3): 128 outputs, split-k (2 threads each)
    {
        int oi = t >> 1, half = t & 1;
        int p = oi >> 2, j = oi & 3;
        const float* xr = xs + (p+3)*128 + half*64;
        const float* wc = xp_s + (half*64)*36 + j;
        float acc = 0.0f;
        #pragma unroll 8
        for (int k = 0; k < 64; k += 2) {
            float2 x = *(const float2*)&xr[k];
            acc = fmaf(x.x, wc[k*36],     acc);
            acc = fmaf(x.y, wc[(k+1)*36], acc);
        }
        acc += __shfl_xor_sync(0xffffffffu, acc, 1);
        if (half == 0) dbc_s[p*36 + j] = acc;
    }
    __syncthreads();

    // dt = softplus(dbc[:4] @ dtw^T + dtb); write fused (dt, xconv) float2
    size_t obase = (size_t)((br*BB + b)*LL + p0) * DI;
    #pragma unroll
    for (int it = 0; it < 16; it++) {
        int i = t + it*256;
        int p = i >> 7, d = i & 127;
        float acc = dtb_s[d];
        #pragma unroll
        for (int r = 0; r < 4; r++)
            acc = fmaf(dtw_s[r*128 + d], dbc_s[p*36 + r], acc);
        float sp = (acc > 20.0f) ? acc : log1pf(__expf(acc));
        g_dtx[obase + i] = make_float2(sp, xs[(p+3)*128 + d]);
    }
    // B/C permuted: row*32 + q*8 + k
    size_t sbase = (size_t)((br*BB + b)*LL + p0) * 32;
    for (int i = t; i < 1024; i += 256) {
        int p = i >> 5, c = i & 31;
        int q = c >> 3, k = c & 7;
        float v = (k < 4) ? dbc_s[p*36 + 4  + q + 4*k]
                          : dbc_s[p*36 + 20 + q + 4*(k-4)];
        g_bc[sbase + i] = v;
    }
}

// ============================================================================
// Kernel 4a: scan pass 1 — per-chunk (P, q), chunks 0..4.
// grid (4 dg * 5 ch, 16, 3) = 960 blocks, 128 thr = 32 d x 4 q.
// ============================================================================
__global__ __launch_bounds__(128) void k_scan1(AP P)
{
    int bx = blockIdx.x;
    int dg = bx / 5, ch = bx - dg*5;
    int b = blockIdx.y, br = blockIdx.z;
    int d0 = dg * 32;
    int t  = threadIdx.x;
    int dl = t >> 2, q = t & 3;
    int d  = d0 + dl;

    float A[4], h[4] = {0,0,0,0}, Pp[4] = {1,1,1,1};
    #pragma unroll
    for (int k = 0; k < 4; k++) A[k] = __ldg(g_A + br*2048 + d*DS + q + 4*k);

    __shared__ __align__(16) float2 sdtx[STG*32];
    __shared__ __align__(16) float  sb[STG*16];

    int bb = br*BB + b;
    size_t rbase = (size_t)bb * LL;

    for (int sub = 0; sub < 2; sub++) {
        int q0 = ch*CHL + sub*STG;
        __syncthreads();
        for (int i = t; i < STG*32; i += 128) {
            int tt = i >> 5, dd = i & 31;
            sdtx[i] = g_dtx[(rbase + q0 + tt)*DI + d0 + dd];
        }
        for (int i = t; i < STG*16; i += 128) {
            int tt = i >> 4, c = i & 15;
            sb[i] = g_bc[(rbase + q0 + tt)*32 + (c>>2)*8 + (c&3)];
        }
        __syncthreads();

        for (int tb = 0; tb < STG; tb += 4) {
            float2 dx[4]; float4 bq[4];
            #pragma unroll
            for (int j = 0; j < 4; j++) {
                dx[j] = sdtx[(tb+j)*32 + dl];
                bq[j] = *(const float4*)&sb[((tb+j)*4 + q)*4];
            }
            float e[4][4];
            #pragma unroll
            for (int j = 0; j < 4; j++) {
                e[j][0] = __expf(dx[j].x*A[0]);
                e[j][1] = __expf(dx[j].x*A[1]);
                e[j][2] = __expf(dx[j].x*A[2]);
                e[j][3] = __expf(dx[j].x*A[3]);
            }
            #pragma unroll
            for (int j = 0; j < 4; j++) {
                float u = dx[j].x * dx[j].y;
                h[0] = fmaf(e[j][0], h[0], bq[j].x * u);
                h[1] = fmaf(e[j][1], h[1], bq[j].y * u);
                h[2] = fmaf(e[j][2], h[2], bq[j].z * u);
                h[3] = fmaf(e[j][3], h[3], bq[j].w * u);
            }
            #pragma unroll
            for (int k = 0; k < 4; k++)
                Pp[k] *= (e[0][k]*e[1][k])*(e[2][k]*e[3][k]);
        }
    }
    size_t pidx = ((size_t)(bb*5 + ch))*2048 + (size_t)d*16 + q;
    #pragma unroll
    for (int k = 0; k < 4; k++) {
        g_P[pidx + 4*k] = Pp[k];
        g_q[pidx + 4*k] = h[k];
    }
}

// ============================================================================
// Kernel 4b: scan pass 2 — inline boundary combine; per-(row,dg) partial dots
// against v. grid (4 dg * 6 ch, 16, 3) = 1152 blocks, 128 thr.
// ============================================================================
__global__ __launch_bounds__(128) void k_scan2(AP P)
{
    int bx = blockIdx.x;
    int dg = bx / 6, ch = bx - dg*6;
    int b = blockIdx.y, br = blockIdx.z;
    int d0 = dg * 32;
    int t  = threadIdx.x;
    int dl = t >> 2, q = t & 3;
    int d  = d0 + dl;
    const BP Bp = P.br[br];

    float A[4];
    #pragma unroll
    for (int k = 0; k < 4; k++) A[k] = __ldg(g_A + br*2048 + d*DS + q + 4*k);
    float Dp = __ldg(Bp.Dp + d);

    int bb = br*BB + b;
    float h[4] = {0,0,0,0};
    for (int c = 0; c < ch; c++) {
        size_t s = ((size_t)(bb*5 + c))*2048 + (size_t)d*16 + q;
        #pragma unroll
        for (int k = 0; k < 4; k++)
            h[k] = fmaf(g_P[s + 4*k], h[k], g_q[s + 4*k]);
    }

    __shared__ __align__(16) float2 sdtx[STG*32];
    __shared__ __align__(16) float  sbc[STG*32];
    __shared__ float sy[STG*32];
    __shared__ float v_s[32];

    if (t < 32) v_s[t] = g_v[d0 + t];

    size_t rbase = (size_t)bb * LL;
    const float* zsrc = g_xz + ((br == 2) ? (size_t)NROW*256 : 0)
                             + (size_t)b*LL*256 + 128 + d0;
    const int rev  = (br == 1);
    const int lb   = rev ? 767 : 0;
    const int lsgn = rev ? -1 : 1;

    for (int sub = 0; sub < 2; sub++) {
        int q0 = ch*CHL + sub*STG;
        __syncthreads();
        for (int i = t; i < STG*32; i += 128) {
            int tt = i >> 5, dd = i & 31;
            sdtx[i] = g_dtx[(rbase + q0 + tt)*DI + d0 + dd];
            sbc[i]  = g_bc [(rbase + q0 + tt)*32 + dd];
        }
        __syncthreads();

        for (int tb = 0; tb < STG; tb += 4) {
            float2 dx[4]; float4 bq[4], cq[4]; float py[4];
            #pragma unroll
            for (int j = 0; j < 4; j++) {
                dx[j] = sdtx[(tb+j)*32 + dl];
                bq[j] = *(const float4*)&sbc[(tb+j)*32 + q*8];
                cq[j] = *(const float4*)&sbc[(tb+j)*32 + q*8 + 4];
            }
            float e[4][4];
            #pragma unroll
            for (int j = 0; j < 4; j++) {
                e[j][0] = __expf(dx[j].x*A[0]);
                e[j][1] = __expf(dx[j].x*A[1]);
                e[j][2] = __expf(dx[j].x*A[2]);
                e[j][3] = __expf(dx[j].x*A[3]);
            }
            #pragma unroll
            for (int j = 0; j < 4; j++) {
                float u = dx[j].x * dx[j].y;
                h[0] = fmaf(e[j][0], h[0], bq[j].x * u);
                h[1] = fmaf(e[j][1], h[1], bq[j].y * u);
                h[2] = fmaf(e[j][2], h[2], bq[j].z * u);
                h[3] = fmaf(e[j][3], h[3], bq[j].w * u);
                float p = h[0]*cq[j].x;
                p = fmaf(h[1], cq[j].y, p);
                p = fmaf(h[2], cq[j].z, p);
                py[j] = fmaf(h[3], cq[j].w, p);
            }
            #pragma unroll
            for (int j = 0; j < 4; j++) {
                py[j] += __shfl_xor_sync(0xffffffffu, py[j], 2);
                py[j] += __shfl_xor_sync(0xffffffffu, py[j], 1);
            }
            if (q == 0) {
                #pragma unroll
                for (int j = 0; j < 4; j++)
                    sy[(tb+j)*32 + dl] = fmaf(dx[j].y, Dp, py[j]);
            }
        }
        __syncthreads();

        // gated partial dot with v: 2 threads per row, 16 d's each
        {
            int row  = t >> 1, half = t & 1;
            int qq   = q0 + row;
            int l    = lb + lsgn*qq;
            const float* zr = zsrc + (size_t)l*256 + half*16;
            const float* yr = sy + row*32 + half*16;
            const float* vr = v_s + half*16;
            float acc = 0.0f;
            #pragma unroll
            for (int dd = 0; dd < 16; dd++) {
                float zv = zr[dd];
                float sg = zv / (1.0f + __expf(-zv));
                acc = fmaf(yr[dd]*sg, vr[dd], acc);
            }
            acc += __shfl_xor_sync(0xffffffffu, acc, 1);
            if (half == 0)
                g_part[((size_t)(b*LL + l))*12 + br*4 + dg] = acc;
        }
    }
}

// ============================================================================
// Kernel 5: att = sigmoid((sum of 12 partials + post_b)/2) + 1e-6
// ============================================================================
__global__ __launch_bounds__(256) void k_final(
    const float* __restrict__ pb, float* __restrict__ out)
{
    int row = blockIdx.x*256 + threadIdx.x;
    const float4* p = (const float4*)(g_part + (size_t)row*12);
    float4 a = p[0], b4 = p[1], c = p[2];
    float s = (a.x+a.y)+(a.z+a.w) + (b4.x+b4.y)+(b4.z+b4.w) + (c.x+c.y)+(c.z+c.w);
    float o = (s + __ldg(pb)) * 0.5f;
    out[row] = 1.0f / (1.0f + __expf(-o)) + 1e-6f;
}

// ============================================================================
extern "C" void kernel_launch(void* const* d_in, const int* in_sizes, int n_in,
                              void* d_out, int out_size)
{
    const float* img1 = (const float*)d_in[0];
    const float* img2 = (const float*)d_in[1];
    const float* pre_w = (const float*)d_in[2];
    const float* pre_b = (const float*)d_in[3];
    const float* ln_g  = (const float*)d_in[4];
    const float* ln_b  = (const float*)d_in[5];
    const float* in_proj_w   = (const float*)d_in[6];
    const float* in_proj_s_w = (const float*)d_in[7];
    const float* out_proj_w  = (const float*)d_in[8];
    const float* post_w = (const float*)d_in[9];
    const float* post_b = (const float*)d_in[10];

    AP P;
    for (int t = 0; t < 3; t++) {
        int o = 11 + 7*t;              // f, b, s
        P.br[t].cw   = (const float*)d_in[o+0];
        P.br[t].cb   = (const float*)d_in[o+1];
        P.br[t].xp   = (const float*)d_in[o+2];
        P.br[t].dtw  = (const float*)d_in[o+3];
        P.br[t].dtb  = (const float*)d_in[o+4];
        P.br[t].Alog = (const float*)d_in[o+5];
        P.br[t].Dp   = (const float*)d_in[o+6];
    }

    k_prep_w<<<3, 256>>>(P);
    k_prep_A<<<5, 256>>>(P, in_proj_w, in_proj_s_w, pre_w);
    k_prep_v<<<1, 128>>>(out_proj_w, post_w);
    k_front<<<dim3(48, 16, 2), 256>>>(img1, img2, pre_b, ln_g, ln_b);
    k_conv_proj<<<dim3(24, 16, 3), 256>>>(P);
    k_scan1<<<dim3(20, 16, 3), 128>>>(P);
    k_scan2<<<dim3(24, 16, 3), 128>>>(P);
    k_final<<<48, 256>>>(post_b, (float*)d_out);
    (void)in_sizes; (void)n_in; (void)out_size;
}

// round 13
// speedup vs baseline: 1.2331x; 1.0424x over previous
#include <cuda_runtime.h>
#include <math.h>

// Problem constants
#define BB   16
#define CC   768          // channels == sequence length L
#define LL   768
#define DM   64           // d_model
#define DI   128          // d_inner
#define DS   16           // d_state
#define NROW (BB*CC)      // 12288 rows per image / per branch

#define NCH  6            // scan chunks
#define CHL  128          // chunk length
#define STG  64           // smem staging length (2 subs per chunk)

// ---------------- scratch (device globals; allocation-free rule) ------------
__device__ float  g_xz[2u*NROW*256];     // in_proj outputs, (img, b*L+l, 256)
__device__ float2 g_dtx[3u*NROW*DI];     // (softplus dt, silu(conv x)) per branch, scan order
__device__ float  g_bc[3u*NROW*32];      // B/C permuted: row*32 + q*8 + k
__device__ float  g_v[DI];               // out_proj_w^T @ post_w  (collapsed epilogue)
__device__ float  g_part[(size_t)NROW*12]; // per (b,l): 12 partials (3 br x 4 dg)
// chunked-scan intermediates
__device__ float  g_P[48u*5*2048];       // per-chunk state decay products
__device__ float  g_q[48u*5*2048];       // per-chunk local end states
// prepped weights (linear / transposed, load-friendly layouts)
__device__ float  g_wxp[3u*4608];        // xproj transposed: [br][k*36+j]
__device__ float  g_wcv[3u*512];         // conv w k-major:   [br][kk*128+d]
__device__ float  g_wdt[3u*512];         // dt w r-major:     [br][r*128+d]
__device__ float  g_A  [3u*2048];        // -exp(A_log)*log2(e): [br][d*16+s]
__device__ float  g_wi [2u*16384];       // in_proj transposed: f4[img][q*256+t]
__device__ float  g_pwt[1024];           // pre_w transposed: [q*64+m]

#define LOG2E 1.4426950408889634f

struct BP { const float *cw, *cb, *xp, *dtw, *dtb, *Alog, *Dp; };
struct AP { BP br[3]; };

// ============================================================================
// Prep kernels (tiny, one-time). Launch order keeps k_conv_proj as ncu's 4th.
// ============================================================================
// blocks 0-2: per-branch weight transposes; block 3: v = out_proj^T @ post_w
__global__ __launch_bounds__(256) void k_prep_w(AP P,
    const float* __restrict__ opw, const float* __restrict__ pw)
{
    int bx = blockIdx.x, t = threadIdx.x;
    if (bx < 3) {
        const BP Bp = P.br[bx];
        float* wxp = g_wxp + bx*4608;
        for (int i = t; i < 4608; i += 256) {
            int k = i / 36, j = i - k*36;
            wxp[i] = __ldg(Bp.xp + j*128 + k);     // xproj_w[j][k]
        }
        float* wcv = g_wcv + bx*512;
        float* wdt = g_wdt + bx*512;
        for (int i = t; i < 512; i += 256) {
            int kk = i >> 7, d = i & 127;
            wcv[i] = __ldg(Bp.cw  + d*4 + kk);
            wdt[i] = __ldg(Bp.dtw + d*4 + kk);
        }
    } else if (t < 128) {
        float acc = 0.0f;
        #pragma unroll 8
        for (int m = 0; m < 64; m++) acc = fmaf(__ldg(pw + m), __ldg(opw + m*128 + t), acc);
        g_v[t] = acc;
    }
}

// blocks 0-2: -exp(A_log)*log2e per branch; blocks 3-4: in_proj/pre_w transposes
__global__ __launch_bounds__(256) void k_prep_A(AP P,
    const float* __restrict__ w0, const float* __restrict__ w1,
    const float* __restrict__ pre_w)
{
    int bx = blockIdx.x, t = threadIdx.x;
    if (bx < 3) {
        const float* al = P.br[bx].Alog;
        for (int i = t; i < 2048; i += 256)
            g_A[bx*2048 + i] = -expf(__ldg(al + i)) * LOG2E;
    } else {
        int img = bx - 3;
        const float4* W4 = (const float4*)(img ? w1 : w0);
        float4* dst = (float4*)(g_wi + (size_t)img*16384);
        #pragma unroll
        for (int q = 0; q < 16; q++)
            dst[q*256 + t] = __ldg(W4 + t*16 + q);   // [q][t] = W[t][4q..]
        if (img == 0) {
            for (int i = t; i < 1024; i += 256) {
                int q = i >> 6, m = i & 63;
                g_pwt[i] = __ldg(pre_w + m*16 + q);
            }
        }
    }
}

// ============================================================================
// Kernel 1 (fused front): pool, pre-proj, LN, in_proj. grid (48,16,2), 256 thr.
// Phase-3 GEMM streams W in two 32-register halves with 16 persistent row
// accumulators -> ~60 regs, 3 blocks/SM (was 98 regs / 2 blocks).
// ============================================================================
__global__ __launch_bounds__(256, 3) void k_front(
    const float* __restrict__ img1, const float* __restrict__ img2,
    const float* __restrict__ pre_b,
    const float* __restrict__ ln_g,  const float* __restrict__ ln_b)
{
    int img = blockIdx.z, b = blockIdx.y, c0 = blockIdx.x * 16;
    const float* src = (img ? img2 : img1) + ((size_t)(b*CC + c0)) * 1024;

    // part_s padded layout: addr(c, t) = c*296 + (t>>6)*72 + (t&63)
    __shared__ float part_s[16*296];
    __shared__ float pw_s[16*64];        // transposed: pw_s[q*64+m]
    __shared__ float pb_s[64], lg_s[64], lb_s[64];
    __shared__ float pool_s[16*16];
    __shared__ __align__(16) float xrow[16*64];

    int t = threadIdx.x;
    for (int i = t; i < 1024; i += 256) pw_s[i] = g_pwt[i];
    if (t < 64) { pb_s[t] = __ldg(pre_b+t); lg_s[t] = __ldg(ln_g+t); lb_s[t] = __ldg(ln_b+t); }

    // phase 1a: coalesced float4 loads; one partial per load
    {
        const float4* s4 = (const float4*)src;
        int toff = (t >> 6)*72 + (t & 63);
        #pragma unroll
        for (int i = 0; i < 16; i++) {
            float4 a = __ldg(s4 + i*256 + t);
            part_s[i*296 + toff] = (a.x + a.y) + (a.z + a.w);
        }
    }
    __syncthreads();

    // phase 1b: reduce 16 contributors per (channel, cell)
    {
        int c = t >> 4, cell = t & 15;
        int pi = cell >> 2, pj = cell & 3;
        const float* base = part_s + c*296 + pi*72 + 2*pj;
        float s = 0.0f;
        #pragma unroll
        for (int k = 0; k < 8; k++) s += base[8*k] + base[8*k + 1];
        pool_s[c*16 + cell] = s * (1.0f/64.0f);
    }
    __syncthreads();

    // phase 2: pre-proj + LN. 16 threads/row, thread g owns m = g+16k
    {
        int r = t >> 4, g = t & 15;
        float y[4], sum = 0.0f, sq = 0.0f;
        #pragma unroll
        for (int k = 0; k < 4; k++) {
            int m = g + 16*k;
            float acc = pb_s[m];
            #pragma unroll
            for (int q = 0; q < 16; q++)
                acc = fmaf(pw_s[q*64 + m], pool_s[r*16 + q], acc);
            y[k] = acc; sum += acc; sq = fmaf(acc, acc, sq);
        }
        #pragma unroll
        for (int m = 8; m >= 1; m >>= 1) {
            sum += __shfl_xor_sync(0xffffffffu, sum, m);
            sq  += __shfl_xor_sync(0xffffffffu, sq,  m);
        }
        float mu  = sum * (1.0f/64.0f);
        float var = sq  * (1.0f/64.0f) - mu*mu;
        float rs  = rsqrtf(var + 1e-5f);
        #pragma unroll
        for (int k = 0; k < 4; k++) {
            int m = g + 16*k;
            xrow[r*64 + m] = (y[k] - mu)*rs*lg_s[m] + lb_s[m];
        }
    }
    __syncthreads();

    // phase 3: xz GEMM, W streamed in 2 halves, 16 persistent accumulators
    {
        const float4* W4 = (const float4*)(g_wi + (size_t)img*16384);
        float a[16];
        #pragma unroll
        for (int r = 0; r < 16; r++) a[r] = 0.0f;

        #pragma unroll
        for (int half = 0; half < 2; half++) {
            float w[32];
            #pragma unroll
            for (int q = 0; q < 8; q++) {
                float4 v = W4[(half*8 + q)*256 + t];
                w[4*q]=v.x; w[4*q+1]=v.y; w[4*q+2]=v.z; w[4*q+3]=v.w;
            }
            #pragma unroll
            for (int r = 0; r < 16; r++) {
                float acc = a[r];
                #pragma unroll
                for (int q = 0; q < 8; q++) {
                    float4 x = *(const float4*)&xrow[r*64 + (half*8 + q)*4];
                    acc = fmaf(x.x, w[4*q],   acc);
                    acc = fmaf(x.y, w[4*q+1], acc);
                    acc = fmaf(x.z, w[4*q+2], acc);
                    acc = fmaf(x.w, w[4*q+3], acc);
                }
                a[r] = acc;
            }
        }
        float* xzout = g_xz + (size_t)img*NROW*256 + ((size_t)(b*CC + c0))*256;
        #pragma unroll
        for (int r = 0; r < 16; r++)
            xzout[(size_t)r*256 + t] = a[r];
    }
}

// ============================================================================
// Kernel 3: causal depthwise conv(K=4)+silu, x-proj (128->36), dt-proj+softplus.
// ============================================================================
__global__ __launch_bounds__(256) void k_conv_proj(AP P)
{
    int br = blockIdx.z, b = blockIdx.y;
    int p0 = blockIdx.x * 32;
    const BP Bp = P.br[br];

    __shared__ __align__(16) float xs[35*128];
    __shared__ __align__(16) float xp_s[128*36];
    __shared__ float dbc_s[32*36];
    __shared__ __align__(16) float cw_s[512];
    __shared__ __align__(16) float dtw_s[512];
    __shared__ __align__(16) float cb_s[128], dtb_s[128];

    int t = threadIdx.x;
    {   // vectorized weight staging from prepped linear arrays (L2-hot)
        const float4* wsrc = (const float4*)(g_wxp + br*4608);
        #pragma unroll
        for (int i0 = 0; i0 < 1152; i0 += 256) ((float4*)xp_s)[i0 + t] = wsrc[i0 + t];
        if (t < 128)       ((float4*)cw_s )[t]     = ((const float4*)(g_wcv + br*512))[t];
        else               ((float4*)dtw_s)[t-128] = ((const float4*)(g_wdt + br*512))[t-128];
        if (t < 32)        ((float4*)cb_s )[t]     = __ldg((const float4*)Bp.cb  + t);
        else if (t < 64)   ((float4*)dtb_s)[t-32]  = __ldg((const float4*)Bp.dtb + (t-32));
    }

    const float* xzsrc = g_xz + ((br == 2) ? (size_t)NROW*256 : 0);
    for (int i = t; i < 35*128; i += 256) {
        int r = i >> 7, d = i & 127;
        int p = p0 - 3 + r;
        float v = 0.0f;
        if (p >= 0) {
            int l = (br == 1) ? (767 - p) : p;
            v = xzsrc[(size_t)(b*LL + l)*256 + d];
        }
        xs[i] = v;
    }
    __syncthreads();

    // causal depthwise conv + silu
    float xc[16];
    #pragma unroll
    for (int it = 0; it < 16; it++) {
        int i = t + it*256;
        int p = i >> 7, d = i & 127;
        float acc = cb_s[d];
        #pragma unroll
        for (int kk = 0; kk < 4; kk++)
            acc = fmaf(cw_s[kk*128 + d], xs[(p+kk)*128 + d], acc);
        float sg = 1.0f / (1.0f + __expf(-acc));
        xc[it] = acc * sg;
    }
    __syncthreads();
    #pragma unroll
    for (int it = 0; it < 16; it++) {
        int i = t + it*256;
        int p = i >> 7, d = i & 127;
        xs[(p+3)*128 + d] = xc[it];
    }
    __syncthreads();

    // B/C GEMM: 32 rows x 32 cols (j=4..35), 2x2 tiles, all 256 threads
    {
        int pg = t >> 4, jg = t & 15;
        int p = 2*pg, j = 4 + 2*jg;
        float a00=0.f, a01=0.f, a10=0.f, a11=0.f;
        const float* xr0 = xs + (p+3)*128;
        const float* xr1 = xs + (p+4)*128;
        const float* wc  = xp_s + j;
        #pragma unroll 4
        for (int k = 0; k < 128; k += 2) {
            float2 x0 = *(const float2*)&xr0[k];
            float2 x1 = *(const float2*)&xr1[k];
            float2 u0 = *(const float2*)&wc[k*36];
            float2 u1 = *(const float2*)&wc[(k+1)*36];
            a00 = fmaf(x0.x, u0.x, a00); a01 = fmaf(x0.x, u0.y, a01);
            a10 = fmaf(x1.x, u0.x, a10); a11 = fmaf(x1.x, u0.y, a11);
            a00 = fmaf(x0.y, u1.x, a00); a01 = fmaf(x0.y, u1.y, a01);
            a10 = fmaf(x1.y, u1.x, a10); a11 = fmaf(x1.y, u1.y, a11);
        }
        dbc_s[p*36 + j]       = a00;
        dbc_s[p*36 + j + 1]   = a01;
        dbc_s[(p+1)*36 + j]   = a10;
        dbc_s[(p+1)*36 + j+1] = a11;
    }
    // dt columns (j=0..3): 128 outputs, split-k (2 threads each)
    {
        int oi = t >> 1, half = t & 1;
        int p = oi >> 2, j = oi & 3;
        const float* xr = xs + (p+3)*128 + half*64;
        const float* wc = xp_s + (half*64)*36 + j;
        float acc = 0.0f;
        #pragma unroll 8
        for (int k = 0; k < 64; k += 2) {
            float2 x = *(const float2*)&xr[k];
            acc = fmaf(x.x, wc[k*36],     acc);
            acc = fmaf(x.y, wc[(k+1)*36], acc);
        }
        acc += __shfl_xor_sync(0xffffffffu, acc, 1);
        if (half == 0) dbc_s[p*36 + j] = acc;
    }
    __syncthreads();

    // dt = softplus(dbc[:4] @ dtw^T + dtb); write fused (dt, xconv) float2
    size_t obase = (size_t)((br*BB + b)*LL + p0) * DI;
    #pragma unroll
    for (int it = 0; it < 16; it++) {
        int i = t + it*256;
        int p = i >> 7, d = i & 127;
        float acc = dtb_s[d];
        #pragma unroll
        for (int r = 0; r < 4; r++)
            acc = fmaf(dtw_s[r*128 + d], dbc_s[p*36 + r], acc);
        float sp = (acc > 20.0f) ? acc : log1pf(__expf(acc));
        g_dtx[obase + i] = make_float2(sp, xs[(p+3)*128 + d]);
    }
    // B/C permuted: row*32 + q*8 + k
    size_t sbase = (size_t)((br*BB + b)*LL + p0) * 32;
    for (int i = t; i < 1024; i += 256) {
        int p = i >> 5, c = i & 31;
        int q = c >> 3, k = c & 7;
        float v = (k < 4) ? dbc_s[p*36 + 4  + q + 4*k]
                          : dbc_s[p*36 + 20 + q + 4*(k-4)];
        g_bc[sbase + i] = v;
    }
}

// ============================================================================
// Kernel 4a: scan pass 1 — per-chunk (P, q), chunks 0..4.
// grid (4 dg * 5 ch, 16, 3) = 960 blocks, 128 thr = 32 d x 4 q.
// A carries log2e; exponentials via exp2f (1 MUFU, no extra FMA).
// ============================================================================
__global__ __launch_bounds__(128) void k_scan1(AP P)
{
    int bx = blockIdx.x;
    int dg = bx / 5, ch = bx - dg*5;
    int b = blockIdx.y, br = blockIdx.z;
    int d0 = dg * 32;
    int t  = threadIdx.x;
    int dl = t >> 2, q = t & 3;
    int d  = d0 + dl;

    float A[4], h[4] = {0,0,0,0}, Pp[4] = {1,1,1,1};
    #pragma unroll
    for (int k = 0; k < 4; k++) A[k] = __ldg(g_A + br*2048 + d*DS + q + 4*k);

    __shared__ __align__(16) float2 sdtx[STG*32];
    __shared__ __align__(16) float  sb[STG*16];

    int bb = br*BB + b;
    size_t rbase = (size_t)bb * LL;

    for (int sub = 0; sub < 2; sub++) {
        int q0 = ch*CHL + sub*STG;
        __syncthreads();
        for (int i = t; i < STG*32; i += 128) {
            int tt = i >> 5, dd = i & 31;
            sdtx[i] = g_dtx[(rbase + q0 + tt)*DI + d0 + dd];
        }
        for (int i = t; i < STG*16; i += 128) {
            int tt = i >> 4, c = i & 15;
            sb[i] = g_bc[(rbase + q0 + tt)*32 + (c>>2)*8 + (c&3)];
        }
        __syncthreads();

        for (int tb = 0; tb < STG; tb += 4) {
            float2 dx[4]; float4 bq[4];
            #pragma unroll
            for (int j = 0; j < 4; j++) {
                dx[j] = sdtx[(tb+j)*32 + dl];
                bq[j] = *(const float4*)&sb[((tb+j)*4 + q)*4];
            }
            float e[4][4];
            #pragma unroll
            for (int j = 0; j < 4; j++) {
                e[j][0] = exp2f(dx[j].x*A[0]);
                e[j][1] = exp2f(dx[j].x*A[1]);
                e[j][2] = exp2f(dx[j].x*A[2]);
                e[j][3] = exp2f(dx[j].x*A[3]);
            }
            #pragma unroll
            for (int j = 0; j < 4; j++) {
                float u = dx[j].x * dx[j].y;
                h[0] = fmaf(e[j][0], h[0], bq[j].x * u);
                h[1] = fmaf(e[j][1], h[1], bq[j].y * u);
                h[2] = fmaf(e[j][2], h[2], bq[j].z * u);
                h[3] = fmaf(e[j][3], h[3], bq[j].w * u);
            }
            #pragma unroll
            for (int k = 0; k < 4; k++)
                Pp[k] *= (e[0][k]*e[1][k])*(e[2][k]*e[3][k]);
        }
    }
    size_t pidx = ((size_t)(bb*5 + ch))*2048 + (size_t)d*16 + q;
    #pragma unroll
    for (int k = 0; k < 4; k++) {
        g_P[pidx + 4*k] = Pp[k];
        g_q[pidx + 4*k] = h[k];
    }
}

// ============================================================================
// Kernel 4b: scan pass 2 — inline boundary combine; per-(row,dg) partial dots
// against v. grid (4 dg * 6 ch, 16, 3) = 1152 blocks, 128 thr.
// ============================================================================
__global__ __launch_bounds__(128) void k_scan2(AP P)
{
    int bx = blockIdx.x;
    int dg = bx / 6, ch = bx - dg*6;
    int b = blockIdx.y, br = blockIdx.z;
    int d0 = dg * 32;
    int t  = threadIdx.x;
    int dl = t >> 2, q = t & 3;
    int d  = d0 + dl;
    const BP Bp = P.br[br];

    float A[4];
    #pragma unroll
    for (int k = 0; k < 4; k++) A[k] = __ldg(g_A + br*2048 + d*DS + q + 4*k);
    float Dp = __ldg(Bp.Dp + d);

    int bb = br*BB + b;
    float h[4] = {0,0,0,0};
    for (int c = 0; c < ch; c++) {
        size_t s = ((size_t)(bb*5 + c))*2048 + (size_t)d*16 + q;
        #pragma unroll
        for (int k = 0; k < 4; k++)
            h[k] = fmaf(g_P[s + 4*k], h[k], g_q[s + 4*k]);
    }

    __shared__ __align__(16) float2 sdtx[STG*32];
    __shared__ __align__(16) float  sbc[STG*32];
    __shared__ float sy[STG*32];
    __shared__ float v_s[32];

    if (t < 32) v_s[t] = g_v[d0 + t];

    size_t rbase = (size_t)bb * LL;
    const float* zsrc = g_xz + ((br == 2) ? (size_t)NROW*256 : 0)
                             + (size_t)b*LL*256 + 128 + d0;
    const int rev  = (br == 1);
    const int lb   = rev ? 767 : 0;
    const int lsgn = rev ? -1 : 1;

    for (int sub = 0; sub < 2; sub++) {
        int q0 = ch*CHL + sub*STG;
        __syncthreads();
        for (int i = t; i < STG*32; i += 128) {
            int tt = i >> 5, dd = i & 31;
            sdtx[i] = g_dtx[(rbase + q0 + tt)*DI + d0 + dd];
            sbc[i]  = g_bc [(rbase + q0 + tt)*32 + dd];
        }
        __syncthreads();

        for (int tb = 0; tb < STG; tb += 4) {
            float2 dx[4]; float4 bq[4], cq[4]; float py[4];
            #pragma unroll
            for (int j = 0; j < 4; j++) {
                dx[j] = sdtx[(tb+j)*32 + dl];
                bq[j] = *(const float4*)&sbc[(tb+j)*32 + q*8];
                cq[j] = *(const float4*)&sbc[(tb+j)*32 + q*8 + 4];
            }
            float e[4][4];
            #pragma unroll
            for (int j = 0; j < 4; j++) {
                e[j][0] = exp2f(dx[j].x*A[0]);
                e[j][1] = exp2f(dx[j].x*A[1]);
                e[j][2] = exp2f(dx[j].x*A[2]);
                e[j][3] = exp2f(dx[j].x*A[3]);
            }
            #pragma unroll
            for (int j = 0; j < 4; j++) {
                float u = dx[j].x * dx[j].y;
                h[0] = fmaf(e[j][0], h[0], bq[j].x * u);
                h[1] = fmaf(e[j][1], h[1], bq[j].y * u);
                h[2] = fmaf(e[j][2], h[2], bq[j].z * u);
                h[3] = fmaf(e[j][3], h[3], bq[j].w * u);
                float p = h[0]*cq[j].x;
                p = fmaf(h[1], cq[j].y, p);
                p = fmaf(h[2], cq[j].z, p);
                py[j] = fmaf(h[3], cq[j].w, p);
            }
            #pragma unroll
            for (int j = 0; j < 4; j++) {
                py[j] += __shfl_xor_sync(0xffffffffu, py[j], 2);
                py[j] += __shfl_xor_sync(0xffffffffu, py[j], 1);
            }
            if (q == 0) {
                #pragma unroll
                for (int j = 0; j < 4; j++)
                    sy[(tb+j)*32 + dl] = fmaf(dx[j].y, Dp, py[j]);
            }
        }
        __syncthreads();

        // gated partial dot with v: 2 threads per row, 16 d's each
        {
            int row  = t >> 1, half = t & 1;
            int qq   = q0 + row;
            int l    = lb + lsgn*qq;
            const float* zr = zsrc + (size_t)l*256 + half*16;
            const float* yr = sy + row*32 + half*16;
            const float* vr = v_s + half*16;
            float acc = 0.0f;
            #pragma unroll
            for (int dd = 0; dd < 16; dd++) {
                float zv = zr[dd];
                float sg = zv / (1.0f + __expf(-zv));
                acc = fmaf(yr[dd]*sg, vr[dd], acc);
            }
            acc += __shfl_xor_sync(0xffffffffu, acc, 1);
            if (half == 0)
                g_part[((size_t)(b*LL + l))*12 + br*4 + dg] = acc;
        }
    }
}

// ============================================================================
// Kernel 5: att = sigmoid((sum of 12 partials + post_b)/2) + 1e-6
// ============================================================================
__global__ __launch_bounds__(256) void k_final(
    const float* __restrict__ pb, float* __restrict__ out)
{
    int row = blockIdx.x*256 + threadIdx.x;
    const float4* p = (const float4*)(g_part + (size_t)row*12);
    float4 a = p[0], b4 = p[1], c = p[2];
    float s = (a.x+a.y)+(a.z+a.w) + (b4.x+b4.y)+(b4.z+b4.w) + (c.x+c.y)+(c.z+c.w);
    float o = (s + __ldg(pb)) * 0.5f;
    out[row] = 1.0f / (1.0f + __expf(-o)) + 1e-6f;
}

// ============================================================================
extern "C" void kernel_launch(void* const* d_in, const int* in_sizes, int n_in,
                              void* d_out, int out_size)
{
    const float* img1 = (const float*)d_in[0];
    const float* img2 = (const float*)d_in[1];
    const float* pre_w = (const float*)d_in[2];
    const float* pre_b = (const float*)d_in[3];
    const float* ln_g  = (const float*)d_in[4];
    const float* ln_b  = (const float*)d_in[5];
    const float* in_proj_w   = (const float*)d_in[6];
    const float* in_proj_s_w = (const float*)d_in[7];
    const float* out_proj_w  = (const float*)d_in[8];
    const float* post_w = (const float*)d_in[9];
    const float* post_b = (const float*)d_in[10];

    AP P;
    for (int t = 0; t < 3; t++) {
        int o = 11 + 7*t;              // f, b, s
        P.br[t].cw   = (const float*)d_in[o+0];
        P.br[t].cb   = (const float*)d_in[o+1];
        P.br[t].xp   = (const float*)d_in[o+2];
        P.br[t].dtw  = (const float*)d_in[o+3];
        P.br[t].dtb  = (const float*)d_in[o+4];
        P.br[t].Alog = (const float*)d_in[o+5];
        P.br[t].Dp   = (const float*)d_in[o+6];
    }

    k_prep_w<<<4, 256>>>(P, out_proj_w, post_w);
    k_prep_A<<<5, 256>>>(P, in_proj_w, in_proj_s_w, pre_w);
    k_front<<<dim3(48, 16, 2), 256>>>(img1, img2, pre_b, ln_g, ln_b);
    k_conv_proj<<<dim3(24, 16, 3), 256>>>(P);
    k_scan1<<<dim3(20, 16, 3), 128>>>(P);
    k_scan2<<<dim3(24, 16, 3), 128>>>(P);
    k_final<<<48, 256>>>(post_b, (float*)d_out);
    (void)in_sizes; (void)n_in; (void)out_size;
}

// round 15
// speedup vs baseline: 1.4052x; 1.1396x over previous
#include <cuda_runtime.h>
#include <math.h>

// Problem constants
#define BB   16
#define CC   768          // channels == sequence length L
#define LL   768
#define DM   64           // d_model
#define DI   128          // d_inner
#define DS   16           // d_state
#define NROW (BB*CC)      // 12288 rows per image / per branch

#define NCH  6            // scan chunks
#define CHL  128          // chunk length
#define STG  64           // smem staging length (2 subs per chunk)

// ---------------- scratch (device globals; allocation-free rule) ------------
__device__ float  g_xz[2u*NROW*256];     // in_proj outputs, (img, b*L+l, 256)
__device__ float2 g_dtx[3u*NROW*DI];     // (softplus dt, silu(conv x)) per branch, scan order
__device__ float  g_bc[3u*NROW*32];      // B/C permuted: row*32 + q*8 + k
__device__ float  g_v[DI];               // out_proj_w^T @ post_w  (collapsed epilogue)
__device__ float  g_part[(size_t)NROW*12]; // per (b,l): 12 partials (3 br x 4 dg)
// chunked-scan intermediates
__device__ float  g_P[48u*5*2048];       // per-chunk state decay products
__device__ float  g_q[48u*5*2048];       // per-chunk local end states
// prepped weights (linear / transposed, load-friendly layouts)
__device__ float  g_wxp[3u*4608];        // xproj transposed: [br][k*36+j]
__device__ float  g_wcv[3u*512];         // conv w k-major:   [br][kk*128+d]
__device__ float  g_wdt[3u*512];         // dt w r-major:     [br][r*128+d]
__device__ float  g_A  [3u*2048];        // -exp(A_log)*log2(e): [br][d*16+s]
__device__ float  g_wi [2u*16384];       // in_proj transposed: f4[img][q*256+t]
__device__ float  g_pwt[1024];           // pre_w transposed: [q*64+m]

#define LOG2E 1.4426950408889634f

struct BP { const float *cw, *cb, *xp, *dtw, *dtb, *Alog, *Dp; };
struct AP { BP br[3]; };

// ============================================================================
// Prep kernels (tiny, one-time). Launch order keeps k_conv_proj as ncu's 4th.
// ============================================================================
__global__ __launch_bounds__(256) void k_prep_w(AP P,
    const float* __restrict__ opw, const float* __restrict__ pw)
{
    int bx = blockIdx.x, t = threadIdx.x;
    if (bx < 3) {
        const BP Bp = P.br[bx];
        float* wxp = g_wxp + bx*4608;
        for (int i = t; i < 4608; i += 256) {
            int k = i / 36, j = i - k*36;
            wxp[i] = __ldg(Bp.xp + j*128 + k);     // xproj_w[j][k]
        }
        float* wcv = g_wcv + bx*512;
        float* wdt = g_wdt + bx*512;
        for (int i = t; i < 512; i += 256) {
            int kk = i >> 7, d = i & 127;
            wcv[i] = __ldg(Bp.cw  + d*4 + kk);
            wdt[i] = __ldg(Bp.dtw + d*4 + kk);
        }
    } else if (t < 128) {
        float acc = 0.0f;
        #pragma unroll 8
        for (int m = 0; m < 64; m++) acc = fmaf(__ldg(pw + m), __ldg(opw + m*128 + t), acc);
        g_v[t] = acc;
    }
}

__global__ __launch_bounds__(256) void k_prep_A(AP P,
    const float* __restrict__ w0, const float* __restrict__ w1,
    const float* __restrict__ pre_w)
{
    int bx = blockIdx.x, t = threadIdx.x;
    if (bx < 3) {
        const float* al = P.br[bx].Alog;
        for (int i = t; i < 2048; i += 256)
            g_A[bx*2048 + i] = -expf(__ldg(al + i)) * LOG2E;
    } else {
        int img = bx - 3;
        const float4* W4 = (const float4*)(img ? w1 : w0);
        float4* dst = (float4*)(g_wi + (size_t)img*16384);
        #pragma unroll
        for (int q = 0; q < 16; q++)
            dst[q*256 + t] = __ldg(W4 + t*16 + q);   // [q][t] = W[t][4q..]
        if (img == 0) {
            for (int i = t; i < 1024; i += 256) {
                int q = i >> 6, m = i & 63;
                g_pwt[i] = __ldg(pre_w + m*16 + q);
            }
        }
    }
}

// ============================================================================
// Kernel 1 (fused front): pool, pre-proj, LN, in_proj. grid (48,16,2), 256 thr.
// ============================================================================
__global__ __launch_bounds__(256, 3) void k_front(
    const float* __restrict__ img1, const float* __restrict__ img2,
    const float* __restrict__ pre_b,
    const float* __restrict__ ln_g,  const float* __restrict__ ln_b)
{
    int img = blockIdx.z, b = blockIdx.y, c0 = blockIdx.x * 16;
    const float* src = (img ? img2 : img1) + ((size_t)(b*CC + c0)) * 1024;

    __shared__ float part_s[16*296];
    __shared__ float pw_s[16*64];        // transposed: pw_s[q*64+m]
    __shared__ float pb_s[64], lg_s[64], lb_s[64];
    __shared__ float pool_s[16*16];
    __shared__ __align__(16) float xrow[16*64];

    int t = threadIdx.x;
    for (int i = t; i < 1024; i += 256) pw_s[i] = g_pwt[i];
    if (t < 64) { pb_s[t] = __ldg(pre_b+t); lg_s[t] = __ldg(ln_g+t); lb_s[t] = __ldg(ln_b+t); }

    // phase 1a: coalesced float4 loads; one partial per load
    {
        const float4* s4 = (const float4*)src;
        int toff = (t >> 6)*72 + (t & 63);
        #pragma unroll
        for (int i = 0; i < 16; i++) {
            float4 a = __ldg(s4 + i*256 + t);
            part_s[i*296 + toff] = (a.x + a.y) + (a.z + a.w);
        }
    }
    __syncthreads();

    // phase 1b: reduce 16 contributors per (channel, cell)
    {
        int c = t >> 4, cell = t & 15;
        int pi = cell >> 2, pj = cell & 3;
        const float* base = part_s + c*296 + pi*72 + 2*pj;
        float s = 0.0f;
        #pragma unroll
        for (int k = 0; k < 8; k++) s += base[8*k] + base[8*k + 1];
        pool_s[c*16 + cell] = s * (1.0f/64.0f);
    }
    __syncthreads();

    // phase 2: pre-proj + LN
    {
        int r = t >> 4, g = t & 15;
        float y[4], sum = 0.0f, sq = 0.0f;
        #pragma unroll
        for (int k = 0; k < 4; k++) {
            int m = g + 16*k;
            float acc = pb_s[m];
            #pragma unroll
            for (int q = 0; q < 16; q++)
                acc = fmaf(pw_s[q*64 + m], pool_s[r*16 + q], acc);
            y[k] = acc; sum += acc; sq = fmaf(acc, acc, sq);
        }
        #pragma unroll
        for (int m = 8; m >= 1; m >>= 1) {
            sum += __shfl_xor_sync(0xffffffffu, sum, m);
            sq  += __shfl_xor_sync(0xffffffffu, sq,  m);
        }
        float mu  = sum * (1.0f/64.0f);
        float var = sq  * (1.0f/64.0f) - mu*mu;
        float rs  = rsqrtf(var + 1e-5f);
        #pragma unroll
        for (int k = 0; k < 4; k++) {
            int m = g + 16*k;
            xrow[r*64 + m] = (y[k] - mu)*rs*lg_s[m] + lb_s[m];
        }
    }
    __syncthreads();

    // phase 3: xz GEMM, W streamed in 2 halves, 16 persistent accumulators
    {
        const float4* W4 = (const float4*)(g_wi + (size_t)img*16384);
        float a[16];
        #pragma unroll
        for (int r = 0; r < 16; r++) a[r] = 0.0f;

        #pragma unroll
        for (int half = 0; half < 2; half++) {
            float w[32];
            #pragma unroll
            for (int q = 0; q < 8; q++) {
                float4 v = W4[(half*8 + q)*256 + t];
                w[4*q]=v.x; w[4*q+1]=v.y; w[4*q+2]=v.z; w[4*q+3]=v.w;
            }
            #pragma unroll
            for (int r = 0; r < 16; r++) {
                float acc = a[r];
                #pragma unroll
                for (int q = 0; q < 8; q++) {
                    float4 x = *(const float4*)&xrow[r*64 + (half*8 + q)*4];
                    acc = fmaf(x.x, w[4*q],   acc);
                    acc = fmaf(x.y, w[4*q+1], acc);
                    acc = fmaf(x.z, w[4*q+2], acc);
                    acc = fmaf(x.w, w[4*q+3], acc);
                }
                a[r] = acc;
            }
        }
        float* xzout = g_xz + (size_t)img*NROW*256 + ((size_t)(b*CC + c0))*256;
        #pragma unroll
        for (int r = 0; r < 16; r++)
            xzout[(size_t)r*256 + t] = a[r];
    }
}

// ============================================================================
// Kernel 3: causal depthwise conv(K=4)+silu, x-proj (128->36), dt-proj+softplus.
// Staging vectorized (float4, row-level reversal); GEMM unroll widened.
// ============================================================================
__global__ __launch_bounds__(256) void k_conv_proj(AP P)
{
    int br = blockIdx.z, b = blockIdx.y;
    int p0 = blockIdx.x * 32;
    const BP Bp = P.br[br];

    __shared__ __align__(16) float xs[35*128];
    __shared__ __align__(16) float xp_s[128*36];
    __shared__ float dbc_s[32*36];
    __shared__ __align__(16) float cw_s[512];
    __shared__ __align__(16) float dtw_s[512];
    __shared__ __align__(16) float cb_s[128], dtb_s[128];

    int t = threadIdx.x;
    {   // vectorized weight staging from prepped linear arrays (L2-hot)
        const float4* wsrc = (const float4*)(g_wxp + br*4608);
        #pragma unroll
        for (int i0 = 0; i0 < 1152; i0 += 256) ((float4*)xp_s)[i0 + t] = wsrc[i0 + t];
        if (t < 128)       ((float4*)cw_s )[t]     = ((const float4*)(g_wcv + br*512))[t];
        else               ((float4*)dtw_s)[t-128] = ((const float4*)(g_wdt + br*512))[t-128];
        if (t < 32)        ((float4*)cb_s )[t]     = __ldg((const float4*)Bp.cb  + t);
        else if (t < 64)   ((float4*)dtb_s)[t-32]  = __ldg((const float4*)Bp.dtb + (t-32));
    }

    // xs staging, float4: 35 rows x 32 f4; reversal applied per row
    {
        const float* xzsrc = g_xz + ((br == 2) ? (size_t)NROW*256 : 0);
        const int rev = (br == 1);
        for (int i = t; i < 1120; i += 256) {
            int r = i >> 5, d4 = i & 31;
            int p = p0 - 3 + r;
            float4 v = make_float4(0.f, 0.f, 0.f, 0.f);
            if (p >= 0) {
                int l = rev ? (767 - p) : p;
                v = __ldg((const float4*)(xzsrc + (size_t)(b*LL + l)*256) + d4);
            }
            ((float4*)xs)[r*32 + d4] = v;
        }
    }
    __syncthreads();

    // causal depthwise conv + silu
    float xc[16];
    #pragma unroll
    for (int it = 0; it < 16; it++) {
        int i = t + it*256;
        int p = i >> 7, d = i & 127;
        float acc = cb_s[d];
        #pragma unroll
        for (int kk = 0; kk < 4; kk++)
            acc = fmaf(cw_s[kk*128 + d], xs[(p+kk)*128 + d], acc);
        float sg = 1.0f / (1.0f + __expf(-acc));
        xc[it] = acc * sg;
    }
    __syncthreads();
    #pragma unroll
    for (int it = 0; it < 16; it++) {
        int i = t + it*256;
        int p = i >> 7, d = i & 127;
        xs[(p+3)*128 + d] = xc[it];
    }
    __syncthreads();

    // B/C GEMM: 32 rows x 32 cols (j=4..35), 2x2 tiles, all 256 threads
    {
        int pg = t >> 4, jg = t & 15;
        int p = 2*pg, j = 4 + 2*jg;
        float a00=0.f, a01=0.f, a10=0.f, a11=0.f;
        const float* xr0 = xs + (p+3)*128;
        const float* xr1 = xs + (p+4)*128;
        const float* wc  = xp_s + j;
        #pragma unroll 8
        for (int k = 0; k < 128; k += 2) {
            float2 x0 = *(const float2*)&xr0[k];
            float2 x1 = *(const float2*)&xr1[k];
            float2 u0 = *(const float2*)&wc[k*36];
            float2 u1 = *(const float2*)&wc[(k+1)*36];
            a00 = fmaf(x0.x, u0.x, a00); a01 = fmaf(x0.x, u0.y, a01);
            a10 = fmaf(x1.x, u0.x, a10); a11 = fmaf(x1.x, u0.y, a11);
            a00 = fmaf(x0.y, u1.x, a00); a01 = fmaf(x0.y, u1.y, a01);
            a10 = fmaf(x1.y, u1.x, a10); a11 = fmaf(x1.y, u1.y, a11);
        }
        dbc_s[p*36 + j]       = a00;
        dbc_s[p*36 + j + 1]   = a01;
        dbc_s[(p+1)*36 + j]   = a10;
        dbc_s[(p+1)*36 + j+1] = a11;
    }
    // dt columns (j=0..3): 128 outputs, split-k (2 threads each)
    {
        int oi = t >> 1, half = t & 1;
        int p = oi >> 2, j = oi & 3;
        const float* xr = xs + (p+3)*128 + half*64;
        const float* wc = xp_s + (half*64)*36 + j;
        float acc = 0.0f;
        #pragma unroll 8
        for (int k = 0; k < 64; k += 2) {
            float2 x = *(const float2*)&xr[k];
            acc = fmaf(x.x, wc[k*36],     acc);
            acc = fmaf(x.y, wc[(k+1)*36], acc);
        }
        acc += __shfl_xor_sync(0xffffffffu, acc, 1);
        if (half == 0) dbc_s[p*36 + j] = acc;
    }
    __syncthreads();

    // dt = softplus(dbc[:4] @ dtw^T + dtb); write fused (dt, xconv) float2
    size_t obase = (size_t)((br*BB + b)*LL + p0) * DI;
    #pragma unroll
    for (int it = 0; it < 16; it++) {
        int i = t + it*256;
        int p = i >> 7, d = i & 127;
        float acc = dtb_s[d];
        #pragma unroll
        for (int r = 0; r < 4; r++)
            acc = fmaf(dtw_s[r*128 + d], dbc_s[p*36 + r], acc);
        float sp = (acc > 20.0f) ? acc : log1pf(__expf(acc));
        g_dtx[obase + i] = make_float2(sp, xs[(p+3)*128 + d]);
    }
    // B/C permuted: row*32 + q*8 + k
    size_t sbase = (size_t)((br*BB + b)*LL + p0) * 32;
    for (int i = t; i < 1024; i += 256) {
        int p = i >> 5, c = i & 31;
        int q = c >> 3, k = c & 7;
        float v = (k < 4) ? dbc_s[p*36 + 4  + q + 4*k]
                          : dbc_s[p*36 + 20 + q + 4*(k-4)];
        g_bc[sbase + i] = v;
    }
}

// ============================================================================
// Kernel 4a: scan pass 1 — per-chunk (P, q), chunks 0..4.
// grid (4 dg * 5 ch, 16, 3) = 960 blocks, 128 thr = 32 d x 4 q.
// ============================================================================
__global__ __launch_bounds__(128) void k_scan1(AP P)
{
    int bx = blockIdx.x;
    int dg = bx / 5, ch = bx - dg*5;
    int b = blockIdx.y, br = blockIdx.z;
    int d0 = dg * 32;
    int t  = threadIdx.x;
    int dl = t >> 2, q = t & 3;
    int d  = d0 + dl;

    float A[4], h[4] = {0,0,0,0}, Pp[4] = {1,1,1,1};
    #pragma unroll
    for (int k = 0; k < 4; k++) A[k] = __ldg(g_A + br*2048 + d*DS + q + 4*k);

    __shared__ __align__(16) float2 sdtx[STG*32];
    __shared__ __align__(16) float  sb[STG*16];

    int bb = br*BB + b;
    size_t rbase = (size_t)bb * LL;

    for (int sub = 0; sub < 2; sub++) {
        int q0 = ch*CHL + sub*STG;
        __syncthreads();
        // sdtx staged as float4 (2 float2 pairs per load)
        for (int i = t; i < STG*16; i += 128) {
            int tt = i >> 4, d2 = i & 15;
            ((float4*)sdtx)[i] =
                __ldg((const float4*)(g_dtx + (rbase + q0 + tt)*DI + d0) + d2);
        }
        for (int i = t; i < STG*16; i += 128) {
            int tt = i >> 4, c = i & 15;
            sb[i] = g_bc[(rbase + q0 + tt)*32 + (c>>2)*8 + (c&3)];
        }
        __syncthreads();

        for (int tb = 0; tb < STG; tb += 4) {
            float2 dx[4]; float4 bq[4];
            #pragma unroll
            for (int j = 0; j < 4; j++) {
                dx[j] = sdtx[(tb+j)*32 + dl];
                bq[j] = *(const float4*)&sb[((tb+j)*4 + q)*4];
            }
            float e[4][4];
            #pragma unroll
            for (int j = 0; j < 4; j++) {
                e[j][0] = exp2f(dx[j].x*A[0]);
                e[j][1] = exp2f(dx[j].x*A[1]);
                e[j][2] = exp2f(dx[j].x*A[2]);
                e[j][3] = exp2f(dx[j].x*A[3]);
            }
            #pragma unroll
            for (int j = 0; j < 4; j++) {
                float u = dx[j].x * dx[j].y;
                h[0] = fmaf(e[j][0], h[0], bq[j].x * u);
                h[1] = fmaf(e[j][1], h[1], bq[j].y * u);
                h[2] = fmaf(e[j][2], h[2], bq[j].z * u);
                h[3] = fmaf(e[j][3], h[3], bq[j].w * u);
            }
            #pragma unroll
            for (int k = 0; k < 4; k++)
                Pp[k] *= (e[0][k]*e[1][k])*(e[2][k]*e[3][k]);
        }
    }
    size_t pidx = ((size_t)(bb*5 + ch))*2048 + (size_t)d*16 + q;
    #pragma unroll
    for (int k = 0; k < 4; k++) {
        g_P[pidx + 4*k] = Pp[k];
        g_q[pidx + 4*k] = h[k];
    }
}

// ============================================================================
// Kernel 4b: scan pass 2 — inline boundary combine; per-(row,dg) partial dots
// against v. grid (4 dg * 6 ch, 16, 3) = 1152 blocks, 128 thr.
// ============================================================================
__global__ __launch_bounds__(128) void k_scan2(AP P)
{
    int bx = blockIdx.x;
    int dg = bx / 6, ch = bx - dg*6;
    int b = blockIdx.y, br = blockIdx.z;
    int d0 = dg * 32;
    int t  = threadIdx.x;
    int dl = t >> 2, q = t & 3;
    int d  = d0 + dl;
    const BP Bp = P.br[br];

    float A[4];
    #pragma unroll
    for (int k = 0; k < 4; k++) A[k] = __ldg(g_A + br*2048 + d*DS + q + 4*k);
    float Dp = __ldg(Bp.Dp + d);

    int bb = br*BB + b;
    float h[4] = {0,0,0,0};
    for (int c = 0; c < ch; c++) {
        size_t s = ((size_t)(bb*5 + c))*2048 + (size_t)d*16 + q;
        #pragma unroll
        for (int k = 0; k < 4; k++)
            h[k] = fmaf(g_P[s + 4*k], h[k], g_q[s + 4*k]);
    }

    __shared__ __align__(16) float2 sdtx[STG*32];
    __shared__ __align__(16) float  sbc[STG*32];
    __shared__ float sy[STG*32];
    __shared__ float v_s[32];

    if (t < 32) v_s[t] = g_v[d0 + t];

    size_t rbase = (size_t)bb * LL;
    const float* zsrc = g_xz + ((br == 2) ? (size_t)NROW*256 : 0)
                             + (size_t)b*LL*256 + 128 + d0;
    const int rev  = (br == 1);
    const int lb   = rev ? 767 : 0;
    const int lsgn = rev ? -1 : 1;

    for (int sub = 0; sub < 2; sub++) {
        int q0 = ch*CHL + sub*STG;
        __syncthreads();
        // float4 staging for both sdtx and sbc
        for (int i = t; i < STG*16; i += 128) {
            int tt = i >> 4, d2 = i & 15;
            ((float4*)sdtx)[i] =
                __ldg((const float4*)(g_dtx + (rbase + q0 + tt)*DI + d0) + d2);
        }
        for (int i = t; i < STG*8; i += 128) {
            int tt = i >> 3, d4 = i & 7;
            ((float4*)sbc)[i] =
                __ldg((const float4*)(g_bc + (rbase + q0 + tt)*32) + d4);
        }
        __syncthreads();

        for (int tb = 0; tb < STG; tb += 4) {
            float2 dx[4]; float4 bq[4], cq[4]; float py[4];
            #pragma unroll
            for (int j = 0; j < 4; j++) {
                dx[j] = sdtx[(tb+j)*32 + dl];
                bq[j] = *(const float4*)&sbc[(tb+j)*32 + q*8];
                cq[j] = *(const float4*)&sbc[(tb+j)*32 + q*8 + 4];
            }
            float e[4][4];
            #pragma unroll
            for (int j = 0; j < 4; j++) {
                e[j][0] = exp2f(dx[j].x*A[0]);
                e[j][1] = exp2f(dx[j].x*A[1]);
                e[j][2] = exp2f(dx[j].x*A[2]);
                e[j][3] = exp2f(dx[j].x*A[3]);
            }
            #pragma unroll
            for (int j = 0; j < 4; j++) {
                float u = dx[j].x * dx[j].y;
                h[0] = fmaf(e[j][0], h[0], bq[j].x * u);
                h[1] = fmaf(e[j][1], h[1], bq[j].y * u);
                h[2] = fmaf(e[j][2], h[2], bq[j].z * u);
                h[3] = fmaf(e[j][3], h[3], bq[j].w * u);
                float p = h[0]*cq[j].x;
                p = fmaf(h[1], cq[j].y, p);
                p = fmaf(h[2], cq[j].z, p);
                py[j] = fmaf(h[3], cq[j].w, p);
            }
            #pragma unroll
            for (int j = 0; j < 4; j++) {
                py[j] += __shfl_xor_sync(0xffffffffu, py[j], 2);
                py[j] += __shfl_xor_sync(0xffffffffu, py[j], 1);
            }
            if (q == 0) {
                #pragma unroll
                for (int j = 0; j < 4; j++)
                    sy[(tb+j)*32 + dl] = fmaf(dx[j].y, Dp, py[j]);
            }
        }
        __syncthreads();

        // gated partial dot with v: 2 threads per row, float4 z loads
        {
            int row  = t >> 1, half = t & 1;
            int qq   = q0 + row;
            int l    = lb + lsgn*qq;
            const float4* zr = (const float4*)(zsrc + (size_t)l*256 + half*16);
            const float4* yr = (const float4*)(sy + row*32 + half*16);
            const float4* vr = (const float4*)(v_s + half*16);
            float acc = 0.0f;
            #pragma unroll
            for (int d4 = 0; d4 < 4; d4++) {
                float4 zv = __ldg(zr + d4);
                float4 yv = yr[d4];
                float4 vv = vr[d4];
                float s0 = zv.x / (1.0f + __expf(-zv.x));
                float s1 = zv.y / (1.0f + __expf(-zv.y));
                float s2 = zv.z / (1.0f + __expf(-zv.z));
                float s3 = zv.w / (1.0f + __expf(-zv.w));
                acc = fmaf(yv.x*s0, vv.x, acc);
                acc = fmaf(yv.y*s1, vv.y, acc);
                acc = fmaf(yv.z*s2, vv.z, acc);
                acc = fmaf(yv.w*s3, vv.w, acc);
            }
            acc += __shfl_xor_sync(0xffffffffu, acc, 1);
            if (half == 0)
                g_part[((size_t)(b*LL + l))*12 + br*4 + dg] = acc;
        }
    }
}

// ============================================================================
// Kernel 5: att = sigmoid((sum of 12 partials + post_b)/2) + 1e-6
// ============================================================================
__global__ __launch_bounds__(256) void k_final(
    const float* __restrict__ pb, float* __restrict__ out)
{
    int row = blockIdx.x*256 + threadIdx.x;
    const float4* p = (const float4*)(g_part + (size_t)row*12);
    float4 a = p[0], b4 = p[1], c = p[2];
    float s = (a.x+a.y)+(a.z+a.w) + (b4.x+b4.y)+(b4.z+b4.w) + (c.x+c.y)+(c.z+c.w);
    float o = (s + __ldg(pb)) * 0.5f;
    out[row] = 1.0f / (1.0f + __expf(-o)) + 1e-6f;
}

// ============================================================================
extern "C" void kernel_launch(void* const* d_in, const int* in_sizes, int n_in,
                              void* d_out, int out_size)
{
    const float* img1 = (const float*)d_in[0];
    const float* img2 = (const float*)d_in[1];
    const float* pre_w = (const float*)d_in[2];
    const float* pre_b = (const float*)d_in[3];
    const float* ln_g  = (const float*)d_in[4];
    const float* ln_b  = (const float*)d_in[5];
    const float* in_proj_w   = (const float*)d_in[6];
    const float* in_proj_s_w = (const float*)d_in[7];
    const float* out_proj_w  = (const float*)d_in[8];
    const float* post_w = (const float*)d_in[9];
    const float* post_b = (const float*)d_in[10];

    AP P;
    for (int t = 0; t < 3; t++) {
        int o = 11 + 7*t;              // f, b, s
        P.br[t].cw   = (const float*)d_in[o+0];
        P.br[t].cb   = (const float*)d_in[o+1];
        P.br[t].xp   = (const float*)d_in[o+2];
        P.br[t].dtw  = (const float*)d_in[o+3];
        P.br[t].dtb  = (const float*)d_in[o+4];
        P.br[t].Alog = (const float*)d_in[o+5];
        P.br[t].Dp   = (const float*)d_in[o+6];
    }

    k_prep_w<<<4, 256>>>(P, out_proj_w, post_w);
    k_prep_A<<<5, 256>>>(P, in_proj_w, in_proj_s_w, pre_w);
    k_front<<<dim3(48, 16, 2), 256>>>(img1, img2, pre_b, ln_g, ln_b);
    k_conv_proj<<<dim3(24, 16, 3), 256>>>(P);
    k_scan1<<<dim3(20, 16, 3), 128>>>(P);
    k_scan2<<<dim3(24, 16, 3), 128>>>(P);
    k_final<<<48, 256>>>(post_b, (float*)d_out);
    (void)in_sizes; (void)n_in; (void)out_size;
}